// round 15
// baseline (speedup 1.0000x reference)
#include <cuda_runtime.h>
#include <cuda_bf16.h>
#include <math.h>

#define NU 100000
#define NI 50000
#define NE 800000
#define BB 1024
typedef unsigned long long ull;

__device__ float g_Eu1[NU*64];
__device__ float g_EuS[NU*64];
__device__ float g_Hg [NU*64];
__device__ float g_hu [NU*64];
__device__ float g_Zu [NU*64];
__device__ float g_Ei1[NI*64];
__device__ float g_EiS[NI*64];
__device__ float g_I1 [NI*64];
__device__ float g_hi [NI*64];
__device__ float g_Zi [NI*64];
__device__ float g_au[NU];
__device__ float g_ai[NI];
__device__ __nv_bfloat16 g_bEu0[NU*64];
__device__ __nv_bfloat16 g_bEu1[NU*64];
__device__ __nv_bfloat16 g_bEuS[NU*64];
__device__ __nv_bfloat16 g_bU1 [NU*64];
__device__ __nv_bfloat16 g_bHg [NU*64];
__device__ __nv_bfloat16 g_bEi0[NI*64];
__device__ __nv_bfloat16 g_bEi1[NI*64];
__device__ __nv_bfloat16 g_bEiS[NI*64];
__device__ float4 g_views4[NE];
__device__ float g_pre[NE];
__device__ int   g_rowptr_u[NU+1];
__device__ int   g_rowptr_i[NI+1];
__device__ int   g_cur_u[NU];
__device__ int   g_cur_i[NI];
__device__ int   g_deg_u[NU];
__device__ int   g_deg_i[NI];
__device__ int   g_part_u[512];
__device__ int   g_part_i[512];
__device__ int   g_hist_u[256], g_hist_i[256];
__device__ int   g_curh_u[256], g_curh_i[256];
__device__ int   g_perm_u[NU], g_perm_i[NI];
__device__ int   g_col_u[NE];
__device__ int   g_col_i[NE];
__device__ int   g_eid_i[NE];
__device__ int   g_pos_u[NE];
__device__ int   g_pos_i[NE];
__device__ float g_fwi[NE], g_fbi[NE], g_wvi[NE];
__device__ float g_wcu[NE],  g_wci[NE];
__device__ float g_wm0u[NE], g_wm1u[NE];
__device__ float g_wm0i[NE], g_wm1i[NE];
__device__ float2 g_wa_u[NE];
__device__ float2 g_wa_i[NE];
__device__ double g_expsum[4];
__device__ double g_acc[4];     // 0: pr, 1: reg, 2: bpr, 3: pos
__device__ double g_negS[2*BB];

__device__ __forceinline__ float sigf(float x){ return 1.f/(1.f+__expf(-x)); }
__device__ __forceinline__ float tanha(float x){
  float y; asm("tanh.approx.f32 %0, %1;":"=f"(y):"f"(x)); return y;
}
__device__ __forceinline__ float ex2a(float x){
  float y; asm("ex2.approx.f32 %0, %1;":"=f"(y):"f"(x)); return y;
}
__device__ __forceinline__ unsigned tf32c(float f){
  unsigned u; asm("cvt.rna.tf32.f32 %0, %1;":"=r"(u):"f"(f)); return u;
}
__device__ __forceinline__ ull fma2(ull a, ull b, ull c){
  ull d;
  asm("fma.rn.f32x2 %0, %1, %2, %3;" : "=l"(d) : "l"(a), "l"(b), "l"(c));
  return d;
}
__device__ __forceinline__ ull bpair(unsigned raw){
  ull d;
  asm("mov.b64 %0,{%1,%2};":"=l"(d):"r"(raw<<16),"r"(raw&0xffff0000u));
  return d;
}
__device__ __forceinline__ float4 b2f4(uint2 raw){
  __nv_bfloat162 b0=*(__nv_bfloat162*)&raw.x, b1=*(__nv_bfloat162*)&raw.y;
  float2 f0=__bfloat1622float2(b0), f1=__bfloat1622float2(b1);
  return make_float4(f0.x,f0.y,f1.x,f1.y);
}
__device__ __forceinline__ uint2 f4b(float4 v){
  __nv_bfloat162 b0=__float22bfloat162_rn(make_float2(v.x,v.y));
  __nv_bfloat162 b1=__float22bfloat162_rn(make_float2(v.z,v.w));
  uint2 r; r.x=*(unsigned*)&b0; r.y=*(unsigned*)&b1; return r;
}
__device__ __forceinline__ float dot4(float4 a, float4 b){
  return a.x*b.x+a.y*b.y+a.z*b.z+a.w*b.w;
}

__global__ void k_init2(const float* __restrict__ Eu0, const float* __restrict__ Ei0,
                        const float* __restrict__ fw, const float* __restrict__ fb,
                        const float* __restrict__ wv,
                        const float* __restrict__ W1u, const float* __restrict__ W1i,
                        const float* __restrict__ b1, const float* __restrict__ W2,
                        const float* __restrict__ b2, const float* __restrict__ att_a,
                        const float* __restrict__ Wg){
  int i0=blockIdx.x*blockDim.x+threadIdx.x, st=gridDim.x*blockDim.x;
  for(int t=i0;t<NU;t+=st) g_deg_u[t]=0;
  for(int t=i0;t<NI;t+=st) g_deg_i[t]=0;
  for(int t=i0;t<2*BB;t+=st) g_negS[t]=0.0;
  if(i0<4){ g_expsum[i0]=0.0; g_acc[i0]=0.0; }
  if(i0<256){ g_hist_u[i0]=0; g_hist_i[i0]=0; }
  double s=0.0;
  for(int i=i0;i<NU*64;i+=st){ float v=Eu0[i]; s+=(double)v*(double)v; }
  for(int i=i0;i<NI*64;i+=st){ float v=Ei0[i]; s+=(double)v*(double)v; }
  for(int i=i0;i<NE;i+=st){
    float x=fw[i],y=fb[i],z=wv[i];
    s+=(double)x*x+(double)y*y+(double)z*z;
  }
  if(blockIdx.x==0){
    const float* ps[7]={W1u,W1i,b1,W2,b2,att_a,Wg};
    const int    ln[7]={4096,4096,64,64,1,128,4096};
    for(int a=0;a<7;a++){
      const float* p=ps[a];
      for(int i=threadIdx.x;i<ln[a];i+=blockDim.x){ float v=p[i]; s+=(double)v*(double)v; }
    }
  }
  #pragma unroll
  for(int o=16;o;o>>=1) s += __shfl_xor_sync(0xffffffffu,s,o);
  if((threadIdx.x&31)==0) atomicAdd(&g_acc[1],s);
}

__global__ void k_count(const int* __restrict__ src, const int* __restrict__ dst){
  int e=blockIdx.x*blockDim.x+threadIdx.x;
  if(e<NE){ atomicAdd(&g_deg_u[src[e]],1); atomicAdd(&g_deg_i[dst[e]],1); }
}

// block-sum of deg (partials) + degree histogram
__global__ void k_scanA(int nbU){
  __shared__ int sh[256];
  __shared__ int hh[256];
  int bu=blockIdx.x<nbU;
  const int* deg = bu? g_deg_u : g_deg_i;
  int* part      = bu? g_part_u: g_part_i;
  int* gh        = bu? g_hist_u: g_hist_i;
  int blk = bu? blockIdx.x : blockIdx.x-nbU;
  int n = bu? NU:NI;
  int i=blk*256+threadIdx.x;
  int v=(i<n)?deg[i]:0;
  sh[threadIdx.x]=v;
  hh[threadIdx.x]=0;
  __syncthreads();
  if(i<n) atomicAdd(&hh[min(v,255)],1);
  for(int o=128;o;o>>=1){ if(threadIdx.x<o) sh[threadIdx.x]+=sh[threadIdx.x+o]; __syncthreads(); }
  if(threadIdx.x==0) part[blk]=sh[0];
  __syncthreads();
  if(hh[threadIdx.x]) atomicAdd(&gh[threadIdx.x],hh[threadIdx.x]);
}
// scan partials (512) + exclusive-scan hist (256)
__global__ void k_scanB(int nbU, int nbI){
  __shared__ int sh[512];
  int* part = blockIdx.x? g_part_i : g_part_u;
  int* hist = blockIdx.x? g_hist_i : g_hist_u;
  int* curh = blockIdx.x? g_curh_i : g_curh_u;
  int nb    = blockIdx.x? nbI : nbU;
  int t=threadIdx.x;
  int v=(t<nb)?part[t]:0;
  sh[t]=v; __syncthreads();
  for(int o=1;o<512;o<<=1){ int a=(t>=o)?sh[t-o]:0; __syncthreads(); sh[t]+=a; __syncthreads(); }
  if(t<nb) part[t]=sh[t]-v;
  __syncthreads();
  int hv=(t<256)?hist[t]:0;
  sh[t]=hv; __syncthreads();
  for(int o=1;o<256;o<<=1){
    int a=(t>=o && t<256)?sh[t-o]:0;
    __syncthreads();
    if(t<256) sh[t]+=a;
    __syncthreads();
  }
  if(t<256){ int ex=sh[t]-hv; hist[t]=ex; curh[t]=ex; }
}
// rowptr + cur + degree-sorted permutation
__global__ void k_scanC(int nbU){
  __shared__ int sh[256];
  int bu=blockIdx.x<nbU;
  const int* deg = bu? g_deg_u : g_deg_i;
  const int* part= bu? g_part_u: g_part_i;
  int* rowptr    = bu? g_rowptr_u : g_rowptr_i;
  int* cur       = bu? g_cur_u : g_cur_i;
  int* curh      = bu? g_curh_u : g_curh_i;
  int* perm      = bu? g_perm_u : g_perm_i;
  int blk = bu? blockIdx.x : blockIdx.x-nbU;
  int n = bu? NU:NI;
  int i=blk*256+threadIdx.x;
  int v=(i<n)?deg[i]:0;
  sh[threadIdx.x]=v; __syncthreads();
  for(int o=1;o<256;o<<=1){ int a=(threadIdx.x>=o)?sh[threadIdx.x-o]:0; __syncthreads(); sh[threadIdx.x]+=a; __syncthreads(); }
  int excl=part[blk]+sh[threadIdx.x]-v;
  if(i<n){
    rowptr[i]=excl; cur[i]=excl;
    int pos=atomicAdd(&curh[min(v,255)],1);
    perm[pos]=i;
  }
  if(i==n-1) rowptr[n]=excl+v;
}

__global__ void k_fill(const int* __restrict__ src, const int* __restrict__ dst,
                       const float* __restrict__ adj, const float* __restrict__ dm,
                       const float* __restrict__ fw, const float* __restrict__ fb,
                       const float* __restrict__ wv){
  int e=blockIdx.x*blockDim.x+threadIdx.x;
  const float R=1.3333333333333333f;
  if(e<NE){
    int s=src[e], d=dst[e];
    float w=adj[e];
    float m0u=(dm[e]      >0.25f)? w*R:0.f;
    float m1u=(dm[2*NE+e] >0.25f)? w*R:0.f;
    float m0i=(dm[NE+e]   >0.25f)? w*R:0.f;
    float m1i=(dm[3*NE+e] >0.25f)? w*R:0.f;
    int p=atomicAdd(&g_cur_u[s],1);
    g_col_u[p]=d; g_wcu[p]=w; g_wm0u[p]=m0u; g_wm1u[p]=m1u;
    g_pos_u[e]=p;
    int q=atomicAdd(&g_cur_i[d],1);
    g_col_i[q]=s; g_eid_i[q]=e; g_wci[q]=w; g_wm0i[q]=m0i; g_wm1i[q]=m1i;
    g_fwi[q]=fw[e]; g_fbi[q]=fb[e]; g_wvi[q]=wv[e];
    g_pos_i[e]=q;
  }
}

// SpMM: 8 warps x 4 perm-sorted rows/warp, 8 lanes/row, LDG.128 bf16 + f32x2 FMA
__device__ __forceinline__ void spmm_body(const int* rowptr, const int* perm, const int* col,
                       const float* w, int ws, int wo, const __nv_bfloat16* X,
                       const float* A, const float* Bv,
                       float* Y, __nv_bfloat16* Yb, int nrows, int blk){
  int tid=threadIdx.x;
  int warp=tid>>5, lane=tid&31;
  int quarter=lane>>3, sub=lane&7;
  int gr=blk*32 + warp*4 + quarter;
  int r = (gr<nrows)? perm[gr] : -1;
  int beg=0,end=0;
  if(r>=0){ beg=rowptr[r]; end=rowptr[r+1]; }
  int deg=end-beg;
  int md=deg;
  md=max(md,__shfl_xor_sync(0xffffffffu,md,8));
  md=max(md,__shfl_xor_sync(0xffffffffu,md,16));
  ull acc[2][4];
  #pragma unroll
  for(int s2=0;s2<2;s2++)
    #pragma unroll
    for(int q=0;q<4;q++) acc[s2][q]=0ull;
  for(int base=0;base<md;base+=8){
    int c=0; float v=0.f;
    if(base+sub<deg){ int j=beg+base+sub; c=col[j]; v=w[j*ws+wo]; }
    #pragma unroll
    for(int q=0;q<8;q++){
      float vq=__shfl_sync(0xffffffffu,v,q,8);
      int   cq=__shfl_sync(0xffffffffu,c,q,8);
      if(vq!=0.f){
        uint4 raw=*(const uint4*)(X+cq*64+sub*8);
        ull v2; asm("mov.b64 %0,{%1,%1};":"=l"(v2):"f"(vq));
        int s2=q&1;
        acc[s2][0]=fma2(bpair(raw.x),v2,acc[s2][0]);
        acc[s2][1]=fma2(bpair(raw.y),v2,acc[s2][1]);
        acc[s2][2]=fma2(bpair(raw.z),v2,acc[s2][2]);
        acc[s2][3]=fma2(bpair(raw.w),v2,acc[s2][3]);
      }
    }
  }
  if(r>=0){
    float f[8];
    #pragma unroll
    for(int q=0;q<4;q++){
      float l0,h0,l1,h1;
      asm("mov.b64 {%0,%1},%2;":"=f"(l0),"=f"(h0):"l"(acc[0][q]));
      asm("mov.b64 {%0,%1},%2;":"=f"(l1),"=f"(h1):"l"(acc[1][q]));
      f[2*q]=l0+l1; f[2*q+1]=h0+h1;
    }
    int o=r*64+sub*8;
    if(A){
      float4 a0=*(const float4*)&A[o], a1=*(const float4*)&A[o+4];
      f[0]+=a0.x; f[1]+=a0.y; f[2]+=a0.z; f[3]+=a0.w;
      f[4]+=a1.x; f[5]+=a1.y; f[6]+=a1.z; f[7]+=a1.w;
    }
    if(Bv){
      float4 b0=*(const float4*)&Bv[o], b1=*(const float4*)&Bv[o+4];
      f[0]+=b0.x; f[1]+=b0.y; f[2]+=b0.z; f[3]+=b0.w;
      f[4]+=b1.x; f[5]+=b1.y; f[6]+=b1.z; f[7]+=b1.w;
    }
    *(float4*)&Y[o]  =make_float4(f[0],f[1],f[2],f[3]);
    *(float4*)&Y[o+4]=make_float4(f[4],f[5],f[6],f[7]);
    if(Yb){
      uint2 p0=f4b(make_float4(f[0],f[1],f[2],f[3]));
      uint2 p1=f4b(make_float4(f[4],f[5],f[6],f[7]));
      uint4 pk; pk.x=p0.x; pk.y=p0.y; pk.z=p1.x; pk.w=p1.y;
      *(uint4*)(Yb+o)=pk;
    }
  }
}
__global__ void k_spmm2(const int* ra, const int* pa, const int* ca, const float* wa, int wsa, int woa,
                        const __nv_bfloat16* Xa,
                        const float* Aa, const float* Ba, float* Ya, __nv_bfloat16* Yba, int na,
                        const int* rb, const int* pb, const int* cb, const float* wb, int wsb, int wob,
                        const __nv_bfloat16* Xb,
                        const float* Ab, const float* Bb, float* Yb, __nv_bfloat16* Ybb, int nb, int gA){
  if((int)blockIdx.x<gA) spmm_body(ra,pa,ca,wa,wsa,woa,Xa,Aa,Ba,Ya,Yba,na,blockIdx.x);
  else                   spmm_body(rb,pb,cb,wb,wsb,wob,Xb,Ab,Bb,Yb,Ybb,nb,blockIdx.x-gA);
}

// node GEMM: 128 rows/block, 8 rows x 4 cols per thread, transposed X tile.
__device__ __forceinline__ void gemm_body(const float* X, const float* W,
                            const float* bias, const float* att,
                            float* Y, __nv_bfloat16* Yb, __nv_bfloat16* Xb,
                            float* attOut, int n, int blk){
  __shared__ float Ws[4096];
  __shared__ float XsT[64][132];
  __shared__ float atts[64];
  int tx=threadIdx.x, ty=threadIdx.y;
  int tid=ty*16+tx;
  for(int t=tid;t<1024;t+=256) ((float4*)Ws)[t]=((const float4*)W)[t];
  if(att && tid<64) atts[tid]=att[tid];
  int rbase=blk*128;
  #pragma unroll
  for(int it=0;it<8;it++){
    int t=tid+256*it;
    int row=t>>4, c16=t&15;
    int r=rbase+row;
    float4 x = (r<n)? ((const float4*)&X[r*64])[c16] : make_float4(0.f,0.f,0.f,0.f);
    int c4=c16*4;
    XsT[c4+0][row]=x.x; XsT[c4+1][row]=x.y; XsT[c4+2][row]=x.z; XsT[c4+3][row]=x.w;
    if(Xb && r<n) *(uint2*)(Xb+r*64+c4)=f4b(x);
  }
  __syncthreads();
  float4 bv = bias ? ((const float4*)bias)[tx] : make_float4(0.f,0.f,0.f,0.f);
  float4 acc[8];
  #pragma unroll
  for(int q=0;q<8;q++) acc[q]=bv;
  #pragma unroll
  for(int k=0;k<64;k++){
    float4 wv=((const float4*)&Ws[k*64])[tx];
    float4 xa=*(const float4*)&XsT[k][ty*8];
    float4 xb2=*(const float4*)&XsT[k][ty*8+4];
    acc[0].x+=xa.x*wv.x; acc[0].y+=xa.x*wv.y; acc[0].z+=xa.x*wv.z; acc[0].w+=xa.x*wv.w;
    acc[1].x+=xa.y*wv.x; acc[1].y+=xa.y*wv.y; acc[1].z+=xa.y*wv.z; acc[1].w+=xa.y*wv.w;
    acc[2].x+=xa.z*wv.x; acc[2].y+=xa.z*wv.y; acc[2].z+=xa.z*wv.z; acc[2].w+=xa.z*wv.w;
    acc[3].x+=xa.w*wv.x; acc[3].y+=xa.w*wv.y; acc[3].z+=xa.w*wv.z; acc[3].w+=xa.w*wv.w;
    acc[4].x+=xb2.x*wv.x; acc[4].y+=xb2.x*wv.y; acc[4].z+=xb2.x*wv.z; acc[4].w+=xb2.x*wv.w;
    acc[5].x+=xb2.y*wv.x; acc[5].y+=xb2.y*wv.y; acc[5].z+=xb2.y*wv.z; acc[5].w+=xb2.y*wv.w;
    acc[6].x+=xb2.z*wv.x; acc[6].y+=xb2.z*wv.y; acc[6].z+=xb2.z*wv.z; acc[6].w+=xb2.z*wv.w;
    acc[7].x+=xb2.w*wv.x; acc[7].y+=xb2.w*wv.y; acc[7].z+=xb2.w*wv.z; acc[7].w+=xb2.w*wv.w;
  }
  #pragma unroll
  for(int q=0;q<8;q++){
    int row=rbase+ty*8+q;
    if(row<n){
      if(Y) ((float4*)&Y[row*64])[tx]=acc[q];
      if(Yb) *(uint2*)(Yb+row*64+tx*4)=f4b(acc[q]);
    }
  }
  if(att){
    #pragma unroll
    for(int q=0;q<8;q++){
      int row=rbase+ty*8+q;
      float p=0.f;
      #pragma unroll
      for(int i=0;i<4;i++) p+=XsT[tx*4+i][ty*8+q]*atts[tx*4+i];
      #pragma unroll
      for(int o=8;o;o>>=1) p+=__shfl_xor_sync(0xffffffffu,p,o,16);
      if(tx==0 && row<n) attOut[row]=p;
    }
  }
}
__global__ void k_gemm2(const float* Xa, const float* Wa, const float* ba, const float* aa,
                        float* Ya, __nv_bfloat16* Yba, __nv_bfloat16* Xba, float* aoa, int na,
                        const float* Xb, const float* Wb, const float* bb, const float* ab,
                        float* Yb, __nv_bfloat16* Ybb, __nv_bfloat16* Xbb, float* aob, int nb, int gA){
  if((int)blockIdx.x<gA) gemm_body(Xa,Wa,ba,aa,Ya,Yba,Xba,aoa,na,blockIdx.x);
  else                   gemm_body(Xb,Wb,bb,ab,Yb,Ybb,Xbb,aob,nb,blockIdx.x-gA);
}

// edge views: warp per item row, 4 edges x 8 lanes x uint4 bf16 gathers
__global__ void k_edge1(const float* __restrict__ W2, const float* __restrict__ b2){
  __shared__ float W2s[64];
  __shared__ double sacc[4];
  int tid=threadIdx.x, lane=tid&31, warp=tid>>5;
  int grp=lane>>3, sub=lane&7;
  if(tid<64) W2s[tid]=W2[tid];
  if(tid<4)  sacc[tid]=0.0;
  __syncthreads();
  int r=blockIdx.x*8+warp;
  float e0=0.f,e1=0.f,e2=0.f,e3=0.f;
  if(r<NI){
    float b2v=b2[0];
    float4 w2a=((const float4*)W2s)[sub*2],  w2b=((const float4*)W2s)[sub*2+1];
    float4 i1a=*(const float4*)&g_I1 [r*64+sub*8], i1b=*(const float4*)&g_I1 [r*64+sub*8+4];
    float4 hia=*(const float4*)&g_hi [r*64+sub*8], hib=*(const float4*)&g_hi [r*64+sub*8+4];
    float4 sia=*(const float4*)&g_EiS[r*64+sub*8], sib=*(const float4*)&g_EiS[r*64+sub*8+4];
    float aiv=g_ai[r];
    int beg=g_rowptr_i[r], end=g_rowptr_i[r+1];
    for(int j0=beg;j0<end;j0+=4){
      int j=j0+grp;
      bool act=(j<end);
      int u=g_col_i[act? j : end-1];
      uint4 ru=*(const uint4*)(g_bU1 +u*64+sub*8);
      uint4 rh=*(const uint4*)(g_bHg +u*64+sub*8);
      uint4 rs=*(const uint4*)(g_bEuS+u*64+sub*8);
      float4 u1a=b2f4(make_uint2(ru.x,ru.y)), u1b=b2f4(make_uint2(ru.z,ru.w));
      float4 hga=b2f4(make_uint2(rh.x,rh.y)), hgb=b2f4(make_uint2(rh.z,rh.w));
      float4 sua=b2f4(make_uint2(rs.x,rs.y)), sub4=b2f4(make_uint2(rs.z,rs.w));
      float m  = fmaxf(u1a.x+i1a.x,0.f)*w2a.x + fmaxf(u1a.y+i1a.y,0.f)*w2a.y
               + fmaxf(u1a.z+i1a.z,0.f)*w2a.z + fmaxf(u1a.w+i1a.w,0.f)*w2a.w
               + fmaxf(u1b.x+i1b.x,0.f)*w2b.x + fmaxf(u1b.y+i1b.y,0.f)*w2b.y
               + fmaxf(u1b.z+i1b.z,0.f)*w2b.z + fmaxf(u1b.w+i1b.w,0.f)*w2b.w;
      float gc = dot4(hga,hia)+dot4(hgb,hib);
      float pr = dot4(sua,sia)+dot4(sub4,sib);
      #pragma unroll
      for(int o=4;o;o>>=1){
        m +=__shfl_xor_sync(0xffffffffu,m,o,8);
        gc+=__shfl_xor_sync(0xffffffffu,gc,o,8);
        pr+=__shfl_xor_sync(0xffffffffu,pr,o,8);
      }
      if(act && sub==0){
        int e=g_eid_i[j];
        float v0=sigf(m+b2v);
        float v1=sigf(g_wvi[j]);
        float v2=sigf(gc);
        float a=g_au[u]+aiv;
        float v3=sigf(a>0.f? a : 0.2f*a);
        g_views4[e]=make_float4(v0,v1,v2,v3);
        g_pre[e]=sigf(pr);
        float w=g_fwi[j], b=g_fbi[j];
        e0+=__expf(tanha(w*v0+b));
        e1+=__expf(tanha(w*v1+b));
        e2+=__expf(tanha(w*v2+b));
        e3+=__expf(tanha(w*v3+b));
      }
    }
  }
  e0+=__shfl_xor_sync(0xffffffffu,e0,8);  e0+=__shfl_xor_sync(0xffffffffu,e0,16);
  e1+=__shfl_xor_sync(0xffffffffu,e1,8);  e1+=__shfl_xor_sync(0xffffffffu,e1,16);
  e2+=__shfl_xor_sync(0xffffffffu,e2,8);  e2+=__shfl_xor_sync(0xffffffffu,e2,16);
  e3+=__shfl_xor_sync(0xffffffffu,e3,8);  e3+=__shfl_xor_sync(0xffffffffu,e3,16);
  if(lane==0 && r<NI){
    atomicAdd(&sacc[0],(double)e0);
    atomicAdd(&sacc[1],(double)e1);
    atomicAdd(&sacc[2],(double)e2);
    atomicAdd(&sacc[3],(double)e3);
  }
  __syncthreads();
  if(tid<4) atomicAdd(&g_expsum[tid],sacc[tid]);
}

__global__ void k_edge2(const float* __restrict__ fw, const float* __restrict__ fb,
                        const float* __restrict__ adj, const float* __restrict__ da){
  int e=blockIdx.x*blockDim.x+threadIdx.x;
  const float R=1.3333333333333333f;
  float lp=0.f;
  if(e<NE){
    float S0=(float)g_expsum[0], S1=(float)g_expsum[1];
    float S2=(float)g_expsum[2], S3=(float)g_expsum[3];
    float w=fw[e], b=fb[e];
    float4 v=g_views4[e];
    float Ag = __expf(tanha(w*v.x+b))/S0*v.x
             + __expf(tanha(w*v.y+b))/S1*v.y
             + __expf(tanha(w*v.z+b))/S2*v.z
             + __expf(tanha(w*v.w+b))/S3*v.w;
    float sumv=v.x+v.y+v.z+v.w;
    float baew=g_pre[e]*((sumv-3.f*Ag)*0.2f);
    float augw=baew*adj[e];
    int pu=g_pos_u[e], pi=g_pos_i[e];
    float a0u=(da[e]      >0.25f)? augw*R:0.f;
    float a1u=(da[2*NE+e] >0.25f)? augw*R:0.f;
    float a0i=(da[NE+e]   >0.25f)? augw*R:0.f;
    float a1i=(da[3*NE+e] >0.25f)? augw*R:0.f;
    g_wa_u[pu]=make_float2(a0u,a1u);
    g_wa_i[pi]=make_float2(a0i,a1i);
    lp=-__logf(baew);
  }
  #pragma unroll
  for(int o=16;o;o>>=1) lp += __shfl_xor_sync(0xffffffffu,lp,o);
  if((threadIdx.x&31)==0) atomicAdd(&g_acc[0],(double)lp);
}

__device__ __forceinline__ void small_body(const int* uids, const int* iids,
                                           const int* pos, const int* neg){
  int warpG=blockIdx.y*8 + (threadIdx.x>>5);
  int l=threadIdx.x&31;
  for(int k=0;k<8;k++){
    int w=warpG+128*k;
    if(w>=BB) break;
    int u=uids[w], it=iids[w], p=pos[w], ng=neg[w];
    float dzu=0,dzi=0,dup=0,dun=0;
    #pragma unroll
    for(int d=l; d<64; d+=32){
      float eu=g_EuS[u*64+d];
      dzu += g_Zu[u*64+d]*eu;
      dzi += g_Zi[it*64+d]*g_EiS[it*64+d];
      dup += eu*g_EiS[p*64+d];
      dun += eu*g_EiS[ng*64+d];
    }
    #pragma unroll
    for(int o=16;o;o>>=1){
      dzu+=__shfl_xor_sync(0xffffffffu,dzu,o);
      dzi+=__shfl_xor_sync(0xffffffffu,dzi,o);
      dup+=__shfl_xor_sync(0xffffffffu,dup,o);
      dun+=__shfl_xor_sync(0xffffffffu,dun,o);
    }
    if(l==0){
      float cu=fminf(fmaxf(dzu*5.f,-5.f),5.f);
      float ci=fminf(fmaxf(dzi*5.f,-5.f),5.f);
      float diff=dup-dun;
      float bpr=fmaxf(-diff,0.f)+log1pf(expf(-fabsf(diff)));
      atomicAdd(&g_acc[3],(double)(cu+ci));
      atomicAdd(&g_acc[2],(double)bpr);
    }
  }
}

// negsum: b64 x j128 tile; X operand from bf16 (raw<<16)
__device__ __forceinline__ void negsum_body(const int* ids, const float* Z,
                                            const __nv_bfloat16* Xb, int N, int isItem, int bx){
  __shared__ unsigned Gs[64][68];
  __shared__ unsigned Xs[128][68];
  __shared__ float Ps[64][8];
  int b0=blockIdx.y*64, j0=bx*128;
  int tid=threadIdx.x;
  const float scale=7.213475204444817f; // log2(e)/0.2
  for(int idx=tid; idx<64*16; idx+=256){
    int r=idx>>4, c4=(idx&15)*4;
    float4 g=*(const float4*)&Z[ids[b0+r]*64+c4];
    Gs[r][c4+0]=tf32c(g.x*scale); Gs[r][c4+1]=tf32c(g.y*scale);
    Gs[r][c4+2]=tf32c(g.z*scale); Gs[r][c4+3]=tf32c(g.w*scale);
  }
  for(int idx=tid; idx<128*16; idx+=256){
    int r=idx>>4, c4=(idx&15)*4;
    int j=j0+r;
    uint2 raw = (j<N)? *(const uint2*)(Xb+j*64+c4) : make_uint2(0u,0u);
    Xs[r][c4+0]=raw.x<<16; Xs[r][c4+1]=raw.x&0xffff0000u;
    Xs[r][c4+2]=raw.y<<16; Xs[r][c4+3]=raw.y&0xffff0000u;
  }
  __syncthreads();
  int w=tid>>5, lane=tid&31;
  int g=lane>>2, t=lane&3;
  int brow=(w&3)*16, jbase=(w>>2)*64;
  float c[8][4];
  #pragma unroll
  for(int nt=0;nt<8;nt++)
    #pragma unroll
    for(int q=0;q<4;q++) c[nt][q]=0.f;
  #pragma unroll
  for(int k0=0;k0<64;k0+=8){
    unsigned a0=Gs[brow+g][k0+t],   a1=Gs[brow+g+8][k0+t];
    unsigned a2=Gs[brow+g][k0+t+4], a3=Gs[brow+g+8][k0+t+4];
    #pragma unroll
    for(int nt=0;nt<8;nt++){
      unsigned bb0=Xs[jbase+nt*8+g][k0+t], bb1=Xs[jbase+nt*8+g][k0+t+4];
      asm volatile("mma.sync.aligned.m16n8k8.row.col.f32.tf32.tf32.f32 "
        "{%0,%1,%2,%3}, {%4,%5,%6,%7}, {%8,%9}, {%0,%1,%2,%3};"
        : "+f"(c[nt][0]),"+f"(c[nt][1]),"+f"(c[nt][2]),"+f"(c[nt][3])
        : "r"(a0),"r"(a1),"r"(a2),"r"(a3),"r"(bb0),"r"(bb1));
    }
  }
  float s0=0.f, s1=0.f;
  #pragma unroll
  for(int nt=0;nt<8;nt++){
    int col=j0+jbase+nt*8+2*t;
    if(col<N)   { s0+=ex2a(c[nt][0]); s1+=ex2a(c[nt][2]); }
    if(col+1<N) { s0+=ex2a(c[nt][1]); s1+=ex2a(c[nt][3]); }
  }
  int slot=(w>>2)*4+t;
  Ps[brow+g][slot]=s0;
  Ps[brow+g+8][slot]=s1;
  __syncthreads();
  if(tid<64){
    float s=0.f;
    #pragma unroll
    for(int q=0;q<8;q++) s+=Ps[tid][q];
    atomicAdd(&g_negS[isItem*BB + b0 + tid],(double)s);
  }
}
__global__ void k_negsum2(const int* uids, const int* iids,
                          const int* pos, const int* neg, int gxU, int gxI){
  if((int)blockIdx.x<gxU) negsum_body(uids,g_Zu,g_bEuS,NU,0,blockIdx.x);
  else if((int)blockIdx.x<gxU+gxI) negsum_body(iids,g_Zi,g_bEiS,NI,1,blockIdx.x-gxU);
  else small_body(uids,iids,pos,neg);
}

__global__ void k_final(float* __restrict__ out){
  __shared__ double sh[1024];
  int t=threadIdx.x;
  sh[t]=log(g_negS[t]+1e-8)+log(g_negS[BB+t]+1e-8);
  __syncthreads();
  for(int o=512;o;o>>=1){ if(t<o) sh[t]+=sh[t+o]; __syncthreads(); }
  if(t==0){
    double neg=sh[0]/(double)BB;
    double pos=g_acc[3]/(double)BB;
    double cl=-pos+neg;
    double bpr=g_acc[2]/(double)BB;
    double pr=0.01*(g_acc[0]/(double)NE);
    double reg=1e-5*g_acc[1];
    out[0]=(float)(bpr+0.2*cl+pr+reg);
    out[1]=(float)bpr;
    out[2]=(float)(0.2*cl);
    out[3]=(float)pr;
  }
}

#define GA(p,s) do{ void* t_=0; cudaGetSymbolAddress(&t_,s); p=(decltype(p))t_; }while(0)

extern "C" void kernel_launch(void* const* d_in, const int* in_sizes, int n_in,
                              void* d_out, int out_size){
  const float* E_u_0 =(const float*)d_in[0];
  const float* E_i_0 =(const float*)d_in[1];
  const float* fuse_w=(const float*)d_in[2];
  const float* fuse_b=(const float*)d_in[3];
  const float* W1u   =(const float*)d_in[4];
  const float* W1i   =(const float*)d_in[5];
  const float* b1    =(const float*)d_in[6];
  const float* W2    =(const float*)d_in[7];
  const float* b2    =(const float*)d_in[8];
  const float* att_a =(const float*)d_in[9];
  const float* wv    =(const float*)d_in[10];
  const float* Wg    =(const float*)d_in[11];
  const float* adj   =(const float*)d_in[12];
  const float* dm    =(const float*)d_in[13];
  const float* da    =(const float*)d_in[14];
  const int* esrc=(const int*)d_in[15];
  const int* edst=(const int*)d_in[16];
  const int* uids=(const int*)d_in[17];
  const int* iids=(const int*)d_in[18];
  const int* pos =(const int*)d_in[19];
  const int* neg =(const int*)d_in[20];
  float* out=(float*)d_out;

  float *Eu1,*EuS,*Hg,*hu,*Zu,*Ei1,*EiS,*I1,*hi,*Zi,*au,*ai;
  float *wcu,*wci,*wm0u,*wm1u,*wm0i,*wm1i;
  float2 *wau,*wai;
  __nv_bfloat16 *bEu0,*bEu1,*bEuS,*bU1,*bHg,*bEi0,*bEi1,*bEiS;
  int *rpu,*rpi,*colu,*coli,*pmu,*pmi;
  GA(Eu1,g_Eu1); GA(EuS,g_EuS); GA(Hg,g_Hg);
  GA(hu,g_hu); GA(Zu,g_Zu); GA(Ei1,g_Ei1); GA(EiS,g_EiS);
  GA(I1,g_I1); GA(hi,g_hi); GA(Zi,g_Zi); GA(au,g_au); GA(ai,g_ai);
  GA(bEu0,g_bEu0); GA(bEu1,g_bEu1); GA(bEuS,g_bEuS); GA(bU1,g_bU1); GA(bHg,g_bHg);
  GA(bEi0,g_bEi0); GA(bEi1,g_bEi1); GA(bEiS,g_bEiS);
  GA(wcu,g_wcu); GA(wci,g_wci); GA(wm0u,g_wm0u); GA(wm1u,g_wm1u);
  GA(wm0i,g_wm0i); GA(wm1i,g_wm1i); GA(wau,g_wa_u); GA(wai,g_wa_i);
  GA(rpu,g_rowptr_u); GA(rpi,g_rowptr_i);
  GA(colu,g_col_u); GA(coli,g_col_i);
  GA(pmu,g_perm_u); GA(pmi,g_perm_i);

  dim3 b256(256), bg(16,16);
  int gU=(NU+31)/32, gI=(NI+31)/32;
  int ggU=(NU+127)/128, ggI=(NI+127)/128;
  int nbU=(NU+255)/256, nbI=(NI+255)/256;

  k_init2<<<512,b256>>>(E_u_0,E_i_0,fuse_w,fuse_b,wv,W1u,W1i,b1,W2,b2,att_a,Wg);
  k_count<<<(NE+255)/256,b256>>>(esrc,edst);
  k_scanA<<<nbU+nbI,b256>>>(nbU);
  k_gemm2<<<ggU+ggI,bg>>>(E_u_0,W1u,b1,att_a, 0,bU1,bEu0,au,NU,
                          E_i_0,W1i,0,att_a+64, I1,0,bEi0,ai,NI,ggU);
  k_scanB<<<2,512>>>(nbU,nbI);
  k_scanC<<<nbU+nbI,b256>>>(nbU);
  k_fill<<<(NE+255)/256,b256>>>(esrc,edst,adj,dm,fuse_w,fuse_b,wv);

  // main propagation
  k_spmm2<<<gU+gI,b256>>>(rpu,pmu,colu,wm0u,1,0,bEi0,0,0,Eu1,bEu1,NU,
                          rpi,pmi,coli,wm0i,1,0,bEu0,0,0,Ei1,bEi1,NI,gU);
  k_spmm2<<<gU+gI,b256>>>(rpu,pmu,colu,wm1u,1,0,bEi1,E_u_0,Eu1,EuS,bEuS,NU,
                          rpi,pmi,coli,wm1i,1,0,bEu1,E_i_0,Ei1,EiS,bEiS,NI,gU);
  // GCN view
  k_spmm2<<<gU+gI,b256>>>(rpu,pmu,colu,wcu,1,0,bEiS,0,0,hu,0,NU,
                          rpi,pmi,coli,wci,1,0,bEuS,0,0,hi,0,NI,gU);
  k_gemm2<<<ggU,bg>>>(hu,Wg,0,0, 0,bHg,0,0,NU, 0,0,0,0,0,0,0,0,0,ggU);

  // edge passes
  k_edge1<<<(NI+7)/8,b256>>>(W2,b2);
  k_edge2<<<(NE+255)/256,b256>>>(fuse_w,fuse_b,adj,da);

  // augmented propagation (paired aug weights, stride-2)
  k_spmm2<<<gU+gI,b256>>>(rpu,pmu,colu,(const float*)wau,2,0,bEi0,0,0,Eu1,bEu1,NU,
                          rpi,pmi,coli,(const float*)wai,2,0,bEu0,0,0,Ei1,bEi1,NI,gU);
  k_spmm2<<<gU+gI,b256>>>(rpu,pmu,colu,(const float*)wau,2,1,bEi1,E_u_0,Eu1,Zu,0,NU,
                          rpi,pmi,coli,(const float*)wai,2,1,bEu1,E_i_0,Ei1,Zi,0,NI,gU);

  // losses (negsum + batch losses in one launch)
  int gxU=(NU+127)/128, gxI=(NI+127)/128;
  k_negsum2<<<dim3(gxU+gxI+1,BB/64),b256>>>(uids,iids,pos,neg,gxU,gxI);

  k_final<<<1,1024>>>(out);
}

// round 16
// speedup vs baseline: 1.4260x; 1.4260x over previous
#include <cuda_runtime.h>
#include <cuda_bf16.h>
#include <math.h>

#define NU 100000
#define NI 50000
#define NE 800000
#define BB 1024
typedef unsigned long long ull;

__device__ float g_Eu1[NU*64];
__device__ float g_EuS[NU*64];
__device__ float g_Hg [NU*64];
__device__ float g_hu [NU*64];
__device__ float g_Zu [NU*64];
__device__ float g_Ei1[NI*64];
__device__ float g_EiS[NI*64];
__device__ float g_I1 [NI*64];
__device__ float g_hi [NI*64];
__device__ float g_Zi [NI*64];
__device__ float g_au[NU];
__device__ float g_ai[NI];
__device__ __nv_bfloat16 g_bEu0[NU*64];
__device__ __nv_bfloat16 g_bEu1[NU*64];
__device__ __nv_bfloat16 g_bEuS[NU*64];
__device__ __nv_bfloat16 g_bU1 [NU*64];
__device__ __nv_bfloat16 g_bHg [NU*64];
__device__ __nv_bfloat16 g_bEi0[NI*64];
__device__ __nv_bfloat16 g_bEi1[NI*64];
__device__ __nv_bfloat16 g_bEiS[NI*64];
__device__ float4 g_views4[NE];
__device__ float g_pre[NE];
__device__ int   g_rowptr_u[NU+1];
__device__ int   g_rowptr_i[NI+1];
__device__ int   g_cur_u[NU];
__device__ int   g_cur_i[NI];
__device__ int   g_deg_u[NU];
__device__ int   g_deg_i[NI];
__device__ int   g_part_u[512];
__device__ int   g_part_i[512];
__device__ int   g_hist_u[256], g_hist_i[256];
__device__ int   g_curh_u[256], g_curh_i[256];
__device__ int   g_perm_u[NU], g_perm_i[NI];
__device__ int   g_col_u[NE];
__device__ int   g_col_i[NE];
__device__ int   g_eid_i[NE];
__device__ int   g_pos_u[NE];
__device__ int   g_pos_i[NE];
__device__ float g_fwi[NE], g_fbi[NE], g_wvi[NE];
__device__ float g_wcu[NE],  g_wci[NE];
__device__ float g_wm0u[NE], g_wm1u[NE];
__device__ float g_wm0i[NE], g_wm1i[NE];
__device__ float2 g_wa_u[NE];
__device__ float2 g_wa_i[NE];
__device__ double g_expsum[4];
__device__ double g_acc[4];     // 0: pr, 1: reg, 2: bpr, 3: pos
__device__ double g_negS[2*BB];

__device__ __forceinline__ float sigf(float x){ return 1.f/(1.f+__expf(-x)); }
__device__ __forceinline__ float tanha(float x){
  float y; asm("tanh.approx.f32 %0, %1;":"=f"(y):"f"(x)); return y;
}
__device__ __forceinline__ float ex2a(float x){
  float y; asm("ex2.approx.f32 %0, %1;":"=f"(y):"f"(x)); return y;
}
__device__ __forceinline__ unsigned tf32c(float f){
  unsigned u; asm("cvt.rna.tf32.f32 %0, %1;":"=r"(u):"f"(f)); return u;
}
__device__ __forceinline__ ull fma2(ull a, ull b, ull c){
  ull d;
  asm("fma.rn.f32x2 %0, %1, %2, %3;" : "=l"(d) : "l"(a), "l"(b), "l"(c));
  return d;
}
__device__ __forceinline__ ull bpair(unsigned raw){
  ull d;
  asm("mov.b64 %0,{%1,%2};":"=l"(d):"r"(raw<<16),"r"(raw&0xffff0000u));
  return d;
}
__device__ __forceinline__ float4 b2f4(uint2 raw){
  __nv_bfloat162 b0=*(__nv_bfloat162*)&raw.x, b1=*(__nv_bfloat162*)&raw.y;
  float2 f0=__bfloat1622float2(b0), f1=__bfloat1622float2(b1);
  return make_float4(f0.x,f0.y,f1.x,f1.y);
}
__device__ __forceinline__ uint2 f4b(float4 v){
  __nv_bfloat162 b0=__float22bfloat162_rn(make_float2(v.x,v.y));
  __nv_bfloat162 b1=__float22bfloat162_rn(make_float2(v.z,v.w));
  uint2 r; r.x=*(unsigned*)&b0; r.y=*(unsigned*)&b1; return r;
}
__device__ __forceinline__ float dot4(float4 a, float4 b){
  return a.x*b.x+a.y*b.y+a.z*b.z+a.w*b.w;
}

__global__ void k_init2(const float* __restrict__ Eu0, const float* __restrict__ Ei0,
                        const float* __restrict__ fw, const float* __restrict__ fb,
                        const float* __restrict__ wv,
                        const float* __restrict__ W1u, const float* __restrict__ W1i,
                        const float* __restrict__ b1, const float* __restrict__ W2,
                        const float* __restrict__ b2, const float* __restrict__ att_a,
                        const float* __restrict__ Wg){
  int i0=blockIdx.x*blockDim.x+threadIdx.x, st=gridDim.x*blockDim.x;
  for(int t=i0;t<NU;t+=st) g_deg_u[t]=0;
  for(int t=i0;t<NI;t+=st) g_deg_i[t]=0;
  for(int t=i0;t<2*BB;t+=st) g_negS[t]=0.0;
  if(i0<4){ g_expsum[i0]=0.0; g_acc[i0]=0.0; }
  if(i0<256){ g_hist_u[i0]=0; g_hist_i[i0]=0; }
  double s=0.0;
  for(int i=i0;i<NU*64;i+=st){ float v=Eu0[i]; s+=(double)v*(double)v; }
  for(int i=i0;i<NI*64;i+=st){ float v=Ei0[i]; s+=(double)v*(double)v; }
  for(int i=i0;i<NE;i+=st){
    float x=fw[i],y=fb[i],z=wv[i];
    s+=(double)x*x+(double)y*y+(double)z*z;
  }
  if(blockIdx.x==0){
    const float* ps[7]={W1u,W1i,b1,W2,b2,att_a,Wg};
    const int    ln[7]={4096,4096,64,64,1,128,4096};
    for(int a=0;a<7;a++){
      const float* p=ps[a];
      for(int i=threadIdx.x;i<ln[a];i+=blockDim.x){ float v=p[i]; s+=(double)v*(double)v; }
    }
  }
  #pragma unroll
  for(int o=16;o;o>>=1) s += __shfl_xor_sync(0xffffffffu,s,o);
  if((threadIdx.x&31)==0) atomicAdd(&g_acc[1],s);
}

__global__ void k_count(const int* __restrict__ src, const int* __restrict__ dst){
  int e=blockIdx.x*blockDim.x+threadIdx.x;
  if(e<NE){ atomicAdd(&g_deg_u[src[e]],1); atomicAdd(&g_deg_i[dst[e]],1); }
}

// block-sum of deg (partials) + degree histogram
__global__ void k_scanA(int nbU){
  __shared__ int sh[256];
  __shared__ int hh[256];
  int bu=blockIdx.x<nbU;
  const int* deg = bu? g_deg_u : g_deg_i;
  int* part      = bu? g_part_u: g_part_i;
  int* gh        = bu? g_hist_u: g_hist_i;
  int blk = bu? blockIdx.x : blockIdx.x-nbU;
  int n = bu? NU:NI;
  int i=blk*256+threadIdx.x;
  int v=(i<n)?deg[i]:0;
  sh[threadIdx.x]=v;
  hh[threadIdx.x]=0;
  __syncthreads();
  if(i<n) atomicAdd(&hh[min(v,255)],1);
  for(int o=128;o;o>>=1){ if(threadIdx.x<o) sh[threadIdx.x]+=sh[threadIdx.x+o]; __syncthreads(); }
  if(threadIdx.x==0) part[blk]=sh[0];
  __syncthreads();
  if(hh[threadIdx.x]) atomicAdd(&gh[threadIdx.x],hh[threadIdx.x]);
}
// scan partials (512) + exclusive-scan hist (256)
__global__ void k_scanB(int nbU, int nbI){
  __shared__ int sh[512];
  int* part = blockIdx.x? g_part_i : g_part_u;
  int* hist = blockIdx.x? g_hist_i : g_hist_u;
  int* curh = blockIdx.x? g_curh_i : g_curh_u;
  int nb    = blockIdx.x? nbI : nbU;
  int t=threadIdx.x;
  int v=(t<nb)?part[t]:0;
  sh[t]=v; __syncthreads();
  for(int o=1;o<512;o<<=1){ int a=(t>=o)?sh[t-o]:0; __syncthreads(); sh[t]+=a; __syncthreads(); }
  if(t<nb) part[t]=sh[t]-v;
  __syncthreads();
  int hv=(t<256)?hist[t]:0;
  sh[t]=hv; __syncthreads();
  for(int o=1;o<256;o<<=1){
    int a=(t>=o && t<256)?sh[t-o]:0;
    __syncthreads();
    if(t<256) sh[t]+=a;
    __syncthreads();
  }
  if(t<256){ int ex=sh[t]-hv; hist[t]=ex; curh[t]=ex; }
}
// rowptr + cur + degree-sorted permutation
__global__ void k_scanC(int nbU){
  __shared__ int sh[256];
  int bu=blockIdx.x<nbU;
  const int* deg = bu? g_deg_u : g_deg_i;
  const int* part= bu? g_part_u: g_part_i;
  int* rowptr    = bu? g_rowptr_u : g_rowptr_i;
  int* cur       = bu? g_cur_u : g_cur_i;
  int* curh      = bu? g_curh_u : g_curh_i;
  int* perm      = bu? g_perm_u : g_perm_i;
  int blk = bu? blockIdx.x : blockIdx.x-nbU;
  int n = bu? NU:NI;
  int i=blk*256+threadIdx.x;
  int v=(i<n)?deg[i]:0;
  sh[threadIdx.x]=v; __syncthreads();
  for(int o=1;o<256;o<<=1){ int a=(threadIdx.x>=o)?sh[threadIdx.x-o]:0; __syncthreads(); sh[threadIdx.x]+=a; __syncthreads(); }
  int excl=part[blk]+sh[threadIdx.x]-v;
  if(i<n){
    rowptr[i]=excl; cur[i]=excl;
    int pos=atomicAdd(&curh[min(v,255)],1);
    perm[pos]=i;
  }
  if(i==n-1) rowptr[n]=excl+v;
}

__global__ void k_fill(const int* __restrict__ src, const int* __restrict__ dst,
                       const float* __restrict__ adj, const float* __restrict__ dm,
                       const float* __restrict__ fw, const float* __restrict__ fb,
                       const float* __restrict__ wv){
  int e=blockIdx.x*blockDim.x+threadIdx.x;
  const float R=1.3333333333333333f;
  if(e<NE){
    int s=src[e], d=dst[e];
    float w=adj[e];
    float m0u=(dm[e]      >0.25f)? w*R:0.f;
    float m1u=(dm[2*NE+e] >0.25f)? w*R:0.f;
    float m0i=(dm[NE+e]   >0.25f)? w*R:0.f;
    float m1i=(dm[3*NE+e] >0.25f)? w*R:0.f;
    int p=atomicAdd(&g_cur_u[s],1);
    g_col_u[p]=d; g_wcu[p]=w; g_wm0u[p]=m0u; g_wm1u[p]=m1u;
    g_pos_u[e]=p;
    int q=atomicAdd(&g_cur_i[d],1);
    g_col_i[q]=s; g_eid_i[q]=e; g_wci[q]=w; g_wm0i[q]=m0i; g_wm1i[q]=m1i;
    g_fwi[q]=fw[e]; g_fbi[q]=fb[e]; g_wvi[q]=wv[e];
    g_pos_i[e]=q;
  }
}

// SpMM: perm-sorted rows processed HIGH-degree-first (wave balance);
// 8 warps x 4 rows/warp, 8 lanes/row, LDG.128 bf16 + f32x2 FMA
__device__ __forceinline__ void spmm_body(const int* rowptr, const int* perm, const int* col,
                       const float* w, int ws, int wo, const __nv_bfloat16* X,
                       const float* A, const float* Bv,
                       float* Y, __nv_bfloat16* Yb, int nrows, int blk){
  int tid=threadIdx.x;
  int warp=tid>>5, lane=tid&31;
  int quarter=lane>>3, sub=lane&7;
  int gr=blk*32 + warp*4 + quarter;
  int r = (gr<nrows)? perm[nrows-1-gr] : -1;
  int beg=0,end=0;
  if(r>=0){ beg=rowptr[r]; end=rowptr[r+1]; }
  int deg=end-beg;
  int md=deg;
  md=max(md,__shfl_xor_sync(0xffffffffu,md,8));
  md=max(md,__shfl_xor_sync(0xffffffffu,md,16));
  ull acc[2][4];
  #pragma unroll
  for(int s2=0;s2<2;s2++)
    #pragma unroll
    for(int q=0;q<4;q++) acc[s2][q]=0ull;
  for(int base=0;base<md;base+=8){
    int c=0; float v=0.f;
    if(base+sub<deg){ int j=beg+base+sub; c=col[j]; v=w[j*ws+wo]; }
    #pragma unroll
    for(int q=0;q<8;q++){
      float vq=__shfl_sync(0xffffffffu,v,q,8);
      int   cq=__shfl_sync(0xffffffffu,c,q,8);
      if(vq!=0.f){
        uint4 raw=*(const uint4*)(X+cq*64+sub*8);
        ull v2; asm("mov.b64 %0,{%1,%1};":"=l"(v2):"f"(vq));
        int s2=q&1;
        acc[s2][0]=fma2(bpair(raw.x),v2,acc[s2][0]);
        acc[s2][1]=fma2(bpair(raw.y),v2,acc[s2][1]);
        acc[s2][2]=fma2(bpair(raw.z),v2,acc[s2][2]);
        acc[s2][3]=fma2(bpair(raw.w),v2,acc[s2][3]);
      }
    }
  }
  if(r>=0){
    float f[8];
    #pragma unroll
    for(int q=0;q<4;q++){
      float l0,h0,l1,h1;
      asm("mov.b64 {%0,%1},%2;":"=f"(l0),"=f"(h0):"l"(acc[0][q]));
      asm("mov.b64 {%0,%1},%2;":"=f"(l1),"=f"(h1):"l"(acc[1][q]));
      f[2*q]=l0+l1; f[2*q+1]=h0+h1;
    }
    int o=r*64+sub*8;
    if(A){
      float4 a0=*(const float4*)&A[o], a1=*(const float4*)&A[o+4];
      f[0]+=a0.x; f[1]+=a0.y; f[2]+=a0.z; f[3]+=a0.w;
      f[4]+=a1.x; f[5]+=a1.y; f[6]+=a1.z; f[7]+=a1.w;
    }
    if(Bv){
      float4 b0=*(const float4*)&Bv[o], b1=*(const float4*)&Bv[o+4];
      f[0]+=b0.x; f[1]+=b0.y; f[2]+=b0.z; f[3]+=b0.w;
      f[4]+=b1.x; f[5]+=b1.y; f[6]+=b1.z; f[7]+=b1.w;
    }
    *(float4*)&Y[o]  =make_float4(f[0],f[1],f[2],f[3]);
    *(float4*)&Y[o+4]=make_float4(f[4],f[5],f[6],f[7]);
    if(Yb){
      uint2 p0=f4b(make_float4(f[0],f[1],f[2],f[3]));
      uint2 p1=f4b(make_float4(f[4],f[5],f[6],f[7]));
      uint4 pk; pk.x=p0.x; pk.y=p0.y; pk.z=p1.x; pk.w=p1.y;
      *(uint4*)(Yb+o)=pk;
    }
  }
}
__global__ void k_spmm2(const int* ra, const int* pa, const int* ca, const float* wa, int wsa, int woa,
                        const __nv_bfloat16* Xa,
                        const float* Aa, const float* Ba, float* Ya, __nv_bfloat16* Yba, int na,
                        const int* rb, const int* pb, const int* cb, const float* wb, int wsb, int wob,
                        const __nv_bfloat16* Xb,
                        const float* Ab, const float* Bb, float* Yb, __nv_bfloat16* Ybb, int nb, int gA){
  if((int)blockIdx.x<gA) spmm_body(ra,pa,ca,wa,wsa,woa,Xa,Aa,Ba,Ya,Yba,na,blockIdx.x);
  else                   spmm_body(rb,pb,cb,wb,wsb,wob,Xb,Ab,Bb,Yb,Ybb,nb,blockIdx.x-gA);
}

// node GEMM: 128 rows/block, 8 rows x 4 cols per thread, transposed X tile.
__device__ __forceinline__ void gemm_body(const float* X, const float* W,
                            const float* bias, const float* att,
                            float* Y, __nv_bfloat16* Yb, __nv_bfloat16* Xb,
                            float* attOut, int n, int blk){
  __shared__ float Ws[4096];
  __shared__ float XsT[64][132];
  __shared__ float atts[64];
  int tx=threadIdx.x, ty=threadIdx.y;
  int tid=ty*16+tx;
  for(int t=tid;t<1024;t+=256) ((float4*)Ws)[t]=((const float4*)W)[t];
  if(att && tid<64) atts[tid]=att[tid];
  int rbase=blk*128;
  #pragma unroll
  for(int it=0;it<8;it++){
    int t=tid+256*it;
    int row=t>>4, c16=t&15;
    int r=rbase+row;
    float4 x = (r<n)? ((const float4*)&X[r*64])[c16] : make_float4(0.f,0.f,0.f,0.f);
    int c4=c16*4;
    XsT[c4+0][row]=x.x; XsT[c4+1][row]=x.y; XsT[c4+2][row]=x.z; XsT[c4+3][row]=x.w;
    if(Xb && r<n) *(uint2*)(Xb+r*64+c4)=f4b(x);
  }
  __syncthreads();
  float4 bv = bias ? ((const float4*)bias)[tx] : make_float4(0.f,0.f,0.f,0.f);
  float4 acc[8];
  #pragma unroll
  for(int q=0;q<8;q++) acc[q]=bv;
  #pragma unroll
  for(int k=0;k<64;k++){
    float4 wv=((const float4*)&Ws[k*64])[tx];
    float4 xa=*(const float4*)&XsT[k][ty*8];
    float4 xb2=*(const float4*)&XsT[k][ty*8+4];
    acc[0].x+=xa.x*wv.x; acc[0].y+=xa.x*wv.y; acc[0].z+=xa.x*wv.z; acc[0].w+=xa.x*wv.w;
    acc[1].x+=xa.y*wv.x; acc[1].y+=xa.y*wv.y; acc[1].z+=xa.y*wv.z; acc[1].w+=xa.y*wv.w;
    acc[2].x+=xa.z*wv.x; acc[2].y+=xa.z*wv.y; acc[2].z+=xa.z*wv.z; acc[2].w+=xa.z*wv.w;
    acc[3].x+=xa.w*wv.x; acc[3].y+=xa.w*wv.y; acc[3].z+=xa.w*wv.z; acc[3].w+=xa.w*wv.w;
    acc[4].x+=xb2.x*wv.x; acc[4].y+=xb2.x*wv.y; acc[4].z+=xb2.x*wv.z; acc[4].w+=xb2.x*wv.w;
    acc[5].x+=xb2.y*wv.x; acc[5].y+=xb2.y*wv.y; acc[5].z+=xb2.y*wv.z; acc[5].w+=xb2.y*wv.w;
    acc[6].x+=xb2.z*wv.x; acc[6].y+=xb2.z*wv.y; acc[6].z+=xb2.z*wv.z; acc[6].w+=xb2.z*wv.w;
    acc[7].x+=xb2.w*wv.x; acc[7].y+=xb2.w*wv.y; acc[7].z+=xb2.w*wv.z; acc[7].w+=xb2.w*wv.w;
  }
  #pragma unroll
  for(int q=0;q<8;q++){
    int row=rbase+ty*8+q;
    if(row<n){
      if(Y) ((float4*)&Y[row*64])[tx]=acc[q];
      if(Yb) *(uint2*)(Yb+row*64+tx*4)=f4b(acc[q]);
    }
  }
  if(att){
    #pragma unroll
    for(int q=0;q<8;q++){
      int row=rbase+ty*8+q;
      float p=0.f;
      #pragma unroll
      for(int i=0;i<4;i++) p+=XsT[tx*4+i][ty*8+q]*atts[tx*4+i];
      #pragma unroll
      for(int o=8;o;o>>=1) p+=__shfl_xor_sync(0xffffffffu,p,o,16);
      if(tx==0 && row<n) attOut[row]=p;
    }
  }
}
__global__ void k_gemm2(const float* Xa, const float* Wa, const float* ba, const float* aa,
                        float* Ya, __nv_bfloat16* Yba, __nv_bfloat16* Xba, float* aoa, int na,
                        const float* Xb, const float* Wb, const float* bb, const float* ab,
                        float* Yb, __nv_bfloat16* Ybb, __nv_bfloat16* Xbb, float* aob, int nb, int gA){
  if((int)blockIdx.x<gA) gemm_body(Xa,Wa,ba,aa,Ya,Yba,Xba,aoa,na,blockIdx.x);
  else                   gemm_body(Xb,Wb,bb,ab,Yb,Ybb,Xbb,aob,nb,blockIdx.x-gA);
}

// edge views: warp per item row, 4 edges x 8 lanes x uint4 bf16 gathers
__global__ void k_edge1(const float* __restrict__ W2, const float* __restrict__ b2){
  __shared__ float W2s[64];
  __shared__ double sacc[4];
  int tid=threadIdx.x, lane=tid&31, warp=tid>>5;
  int grp=lane>>3, sub=lane&7;
  if(tid<64) W2s[tid]=W2[tid];
  if(tid<4)  sacc[tid]=0.0;
  __syncthreads();
  int r=blockIdx.x*8+warp;
  float e0=0.f,e1=0.f,e2=0.f,e3=0.f;
  if(r<NI){
    float b2v=b2[0];
    float4 w2a=((const float4*)W2s)[sub*2],  w2b=((const float4*)W2s)[sub*2+1];
    float4 i1a=*(const float4*)&g_I1 [r*64+sub*8], i1b=*(const float4*)&g_I1 [r*64+sub*8+4];
    float4 hia=*(const float4*)&g_hi [r*64+sub*8], hib=*(const float4*)&g_hi [r*64+sub*8+4];
    float4 sia=*(const float4*)&g_EiS[r*64+sub*8], sib=*(const float4*)&g_EiS[r*64+sub*8+4];
    float aiv=g_ai[r];
    int beg=g_rowptr_i[r], end=g_rowptr_i[r+1];
    for(int j0=beg;j0<end;j0+=4){
      int j=j0+grp;
      bool act=(j<end);
      int u=g_col_i[act? j : end-1];
      uint4 ru=*(const uint4*)(g_bU1 +u*64+sub*8);
      uint4 rh=*(const uint4*)(g_bHg +u*64+sub*8);
      uint4 rs=*(const uint4*)(g_bEuS+u*64+sub*8);
      float4 u1a=b2f4(make_uint2(ru.x,ru.y)), u1b=b2f4(make_uint2(ru.z,ru.w));
      float4 hga=b2f4(make_uint2(rh.x,rh.y)), hgb=b2f4(make_uint2(rh.z,rh.w));
      float4 sua=b2f4(make_uint2(rs.x,rs.y)), sub4=b2f4(make_uint2(rs.z,rs.w));
      float m  = fmaxf(u1a.x+i1a.x,0.f)*w2a.x + fmaxf(u1a.y+i1a.y,0.f)*w2a.y
               + fmaxf(u1a.z+i1a.z,0.f)*w2a.z + fmaxf(u1a.w+i1a.w,0.f)*w2a.w
               + fmaxf(u1b.x+i1b.x,0.f)*w2b.x + fmaxf(u1b.y+i1b.y,0.f)*w2b.y
               + fmaxf(u1b.z+i1b.z,0.f)*w2b.z + fmaxf(u1b.w+i1b.w,0.f)*w2b.w;
      float gc = dot4(hga,hia)+dot4(hgb,hib);
      float pr = dot4(sua,sia)+dot4(sub4,sib);
      #pragma unroll
      for(int o=4;o;o>>=1){
        m +=__shfl_xor_sync(0xffffffffu,m,o,8);
        gc+=__shfl_xor_sync(0xffffffffu,gc,o,8);
        pr+=__shfl_xor_sync(0xffffffffu,pr,o,8);
      }
      if(act && sub==0){
        int e=g_eid_i[j];
        float v0=sigf(m+b2v);
        float v1=sigf(g_wvi[j]);
        float v2=sigf(gc);
        float a=g_au[u]+aiv;
        float v3=sigf(a>0.f? a : 0.2f*a);
        g_views4[e]=make_float4(v0,v1,v2,v3);
        g_pre[e]=sigf(pr);
        float w=g_fwi[j], b=g_fbi[j];
        e0+=__expf(tanha(w*v0+b));
        e1+=__expf(tanha(w*v1+b));
        e2+=__expf(tanha(w*v2+b));
        e3+=__expf(tanha(w*v3+b));
      }
    }
  }
  e0+=__shfl_xor_sync(0xffffffffu,e0,8);  e0+=__shfl_xor_sync(0xffffffffu,e0,16);
  e1+=__shfl_xor_sync(0xffffffffu,e1,8);  e1+=__shfl_xor_sync(0xffffffffu,e1,16);
  e2+=__shfl_xor_sync(0xffffffffu,e2,8);  e2+=__shfl_xor_sync(0xffffffffu,e2,16);
  e3+=__shfl_xor_sync(0xffffffffu,e3,8);  e3+=__shfl_xor_sync(0xffffffffu,e3,16);
  if(lane==0 && r<NI){
    atomicAdd(&sacc[0],(double)e0);
    atomicAdd(&sacc[1],(double)e1);
    atomicAdd(&sacc[2],(double)e2);
    atomicAdd(&sacc[3],(double)e3);
  }
  __syncthreads();
  if(tid<4) atomicAdd(&g_expsum[tid],sacc[tid]);
}

__global__ void k_edge2(const float* __restrict__ fw, const float* __restrict__ fb,
                        const float* __restrict__ adj, const float* __restrict__ da){
  int e=blockIdx.x*blockDim.x+threadIdx.x;
  const float R=1.3333333333333333f;
  float lp=0.f;
  if(e<NE){
    float S0=(float)g_expsum[0], S1=(float)g_expsum[1];
    float S2=(float)g_expsum[2], S3=(float)g_expsum[3];
    float w=fw[e], b=fb[e];
    float4 v=g_views4[e];
    float Ag = __expf(tanha(w*v.x+b))/S0*v.x
             + __expf(tanha(w*v.y+b))/S1*v.y
             + __expf(tanha(w*v.z+b))/S2*v.z
             + __expf(tanha(w*v.w+b))/S3*v.w;
    float sumv=v.x+v.y+v.z+v.w;
    float baew=g_pre[e]*((sumv-3.f*Ag)*0.2f);
    float augw=baew*adj[e];
    int pu=g_pos_u[e], pi=g_pos_i[e];
    float a0u=(da[e]      >0.25f)? augw*R:0.f;
    float a1u=(da[2*NE+e] >0.25f)? augw*R:0.f;
    float a0i=(da[NE+e]   >0.25f)? augw*R:0.f;
    float a1i=(da[3*NE+e] >0.25f)? augw*R:0.f;
    g_wa_u[pu]=make_float2(a0u,a1u);
    g_wa_i[pi]=make_float2(a0i,a1i);
    lp=-__logf(baew);
  }
  #pragma unroll
  for(int o=16;o;o>>=1) lp += __shfl_xor_sync(0xffffffffu,lp,o);
  if((threadIdx.x&31)==0) atomicAdd(&g_acc[0],(double)lp);
}

__device__ __forceinline__ void small_body(const int* uids, const int* iids,
                                           const int* pos, const int* neg){
  int warpG=blockIdx.y*8 + (threadIdx.x>>5);
  int l=threadIdx.x&31;
  for(int k=0;k<8;k++){
    int w=warpG+128*k;
    if(w>=BB) break;
    int u=uids[w], it=iids[w], p=pos[w], ng=neg[w];
    float dzu=0,dzi=0,dup=0,dun=0;
    #pragma unroll
    for(int d=l; d<64; d+=32){
      float eu=g_EuS[u*64+d];
      dzu += g_Zu[u*64+d]*eu;
      dzi += g_Zi[it*64+d]*g_EiS[it*64+d];
      dup += eu*g_EiS[p*64+d];
      dun += eu*g_EiS[ng*64+d];
    }
    #pragma unroll
    for(int o=16;o;o>>=1){
      dzu+=__shfl_xor_sync(0xffffffffu,dzu,o);
      dzi+=__shfl_xor_sync(0xffffffffu,dzi,o);
      dup+=__shfl_xor_sync(0xffffffffu,dup,o);
      dun+=__shfl_xor_sync(0xffffffffu,dun,o);
    }
    if(l==0){
      float cu=fminf(fmaxf(dzu*5.f,-5.f),5.f);
      float ci=fminf(fmaxf(dzi*5.f,-5.f),5.f);
      float diff=dup-dun;
      float bpr=fmaxf(-diff,0.f)+log1pf(expf(-fabsf(diff)));
      atomicAdd(&g_acc[3],(double)(cu+ci));
      atomicAdd(&g_acc[2],(double)bpr);
    }
  }
}

// negsum: b64 x j128 tile; X operand from bf16 (raw<<16)
__device__ __forceinline__ void negsum_body(const int* ids, const float* Z,
                                            const __nv_bfloat16* Xb, int N, int isItem, int bx){
  __shared__ unsigned Gs[64][68];
  __shared__ unsigned Xs[128][68];
  __shared__ float Ps[64][8];
  int b0=blockIdx.y*64, j0=bx*128;
  int tid=threadIdx.x;
  const float scale=7.213475204444817f; // log2(e)/0.2
  for(int idx=tid; idx<64*16; idx+=256){
    int r=idx>>4, c4=(idx&15)*4;
    float4 g=*(const float4*)&Z[ids[b0+r]*64+c4];
    Gs[r][c4+0]=tf32c(g.x*scale); Gs[r][c4+1]=tf32c(g.y*scale);
    Gs[r][c4+2]=tf32c(g.z*scale); Gs[r][c4+3]=tf32c(g.w*scale);
  }
  for(int idx=tid; idx<128*16; idx+=256){
    int r=idx>>4, c4=(idx&15)*4;
    int j=j0+r;
    uint2 raw = (j<N)? *(const uint2*)(Xb+j*64+c4) : make_uint2(0u,0u);
    Xs[r][c4+0]=raw.x<<16; Xs[r][c4+1]=raw.x&0xffff0000u;
    Xs[r][c4+2]=raw.y<<16; Xs[r][c4+3]=raw.y&0xffff0000u;
  }
  __syncthreads();
  int w=tid>>5, lane=tid&31;
  int g=lane>>2, t=lane&3;
  int brow=(w&3)*16, jbase=(w>>2)*64;
  float c[8][4];
  #pragma unroll
  for(int nt=0;nt<8;nt++)
    #pragma unroll
    for(int q=0;q<4;q++) c[nt][q]=0.f;
  #pragma unroll
  for(int k0=0;k0<64;k0+=8){
    unsigned a0=Gs[brow+g][k0+t],   a1=Gs[brow+g+8][k0+t];
    unsigned a2=Gs[brow+g][k0+t+4], a3=Gs[brow+g+8][k0+t+4];
    #pragma unroll
    for(int nt=0;nt<8;nt++){
      unsigned bb0=Xs[jbase+nt*8+g][k0+t], bb1=Xs[jbase+nt*8+g][k0+t+4];
      asm volatile("mma.sync.aligned.m16n8k8.row.col.f32.tf32.tf32.f32 "
        "{%0,%1,%2,%3}, {%4,%5,%6,%7}, {%8,%9}, {%0,%1,%2,%3};"
        : "+f"(c[nt][0]),"+f"(c[nt][1]),"+f"(c[nt][2]),"+f"(c[nt][3])
        : "r"(a0),"r"(a1),"r"(a2),"r"(a3),"r"(bb0),"r"(bb1));
    }
  }
  float s0=0.f, s1=0.f;
  #pragma unroll
  for(int nt=0;nt<8;nt++){
    int col=j0+jbase+nt*8+2*t;
    if(col<N)   { s0+=ex2a(c[nt][0]); s1+=ex2a(c[nt][2]); }
    if(col+1<N) { s0+=ex2a(c[nt][1]); s1+=ex2a(c[nt][3]); }
  }
  int slot=(w>>2)*4+t;
  Ps[brow+g][slot]=s0;
  Ps[brow+g+8][slot]=s1;
  __syncthreads();
  if(tid<64){
    float s=0.f;
    #pragma unroll
    for(int q=0;q<8;q++) s+=Ps[tid][q];
    atomicAdd(&g_negS[isItem*BB + b0 + tid],(double)s);
  }
}
__global__ void k_negsum2(const int* uids, const int* iids,
                          const int* pos, const int* neg, int gxU, int gxI){
  if((int)blockIdx.x<gxU) negsum_body(uids,g_Zu,g_bEuS,NU,0,blockIdx.x);
  else if((int)blockIdx.x<gxU+gxI) negsum_body(iids,g_Zi,g_bEiS,NI,1,blockIdx.x-gxU);
  else small_body(uids,iids,pos,neg);
}

__global__ void k_final(float* __restrict__ out){
  __shared__ double sh[1024];
  int t=threadIdx.x;
  sh[t]=log(g_negS[t]+1e-8)+log(g_negS[BB+t]+1e-8);
  __syncthreads();
  for(int o=512;o;o>>=1){ if(t<o) sh[t]+=sh[t+o]; __syncthreads(); }
  if(t==0){
    double neg=sh[0]/(double)BB;
    double pos=g_acc[3]/(double)BB;
    double cl=-pos+neg;
    double bpr=g_acc[2]/(double)BB;
    double pr=0.01*(g_acc[0]/(double)NE);
    double reg=1e-5*g_acc[1];
    out[0]=(float)(bpr+0.2*cl+pr+reg);
    out[1]=(float)bpr;
    out[2]=(float)(0.2*cl);
    out[3]=(float)pr;
  }
}

#define GA(p,s) do{ void* t_=0; cudaGetSymbolAddress(&t_,s); p=(decltype(p))t_; }while(0)

extern "C" void kernel_launch(void* const* d_in, const int* in_sizes, int n_in,
                              void* d_out, int out_size){
  const float* E_u_0 =(const float*)d_in[0];
  const float* E_i_0 =(const float*)d_in[1];
  const float* fuse_w=(const float*)d_in[2];
  const float* fuse_b=(const float*)d_in[3];
  const float* W1u   =(const float*)d_in[4];
  const float* W1i   =(const float*)d_in[5];
  const float* b1    =(const float*)d_in[6];
  const float* W2    =(const float*)d_in[7];
  const float* b2    =(const float*)d_in[8];
  const float* att_a =(const float*)d_in[9];
  const float* wv    =(const float*)d_in[10];
  const float* Wg    =(const float*)d_in[11];
  const float* adj   =(const float*)d_in[12];
  const float* dm    =(const float*)d_in[13];
  const float* da    =(const float*)d_in[14];
  const int* esrc=(const int*)d_in[15];
  const int* edst=(const int*)d_in[16];
  const int* uids=(const int*)d_in[17];
  const int* iids=(const int*)d_in[18];
  const int* pos =(const int*)d_in[19];
  const int* neg =(const int*)d_in[20];
  float* out=(float*)d_out;

  float *Eu1,*EuS,*Hg,*hu,*Zu,*Ei1,*EiS,*I1,*hi,*Zi,*au,*ai;
  float *wcu,*wci,*wm0u,*wm1u,*wm0i,*wm1i;
  float2 *wau,*wai;
  __nv_bfloat16 *bEu0,*bEu1,*bEuS,*bU1,*bHg,*bEi0,*bEi1,*bEiS;
  int *rpu,*rpi,*colu,*coli,*pmu,*pmi;
  GA(Eu1,g_Eu1); GA(EuS,g_EuS); GA(Hg,g_Hg);
  GA(hu,g_hu); GA(Zu,g_Zu); GA(Ei1,g_Ei1); GA(EiS,g_EiS);
  GA(I1,g_I1); GA(hi,g_hi); GA(Zi,g_Zi); GA(au,g_au); GA(ai,g_ai);
  GA(bEu0,g_bEu0); GA(bEu1,g_bEu1); GA(bEuS,g_bEuS); GA(bU1,g_bU1); GA(bHg,g_bHg);
  GA(bEi0,g_bEi0); GA(bEi1,g_bEi1); GA(bEiS,g_bEiS);
  GA(wcu,g_wcu); GA(wci,g_wci); GA(wm0u,g_wm0u); GA(wm1u,g_wm1u);
  GA(wm0i,g_wm0i); GA(wm1i,g_wm1i); GA(wau,g_wa_u); GA(wai,g_wa_i);
  GA(rpu,g_rowptr_u); GA(rpi,g_rowptr_i);
  GA(colu,g_col_u); GA(coli,g_col_i);
  GA(pmu,g_perm_u); GA(pmi,g_perm_i);

  dim3 b256(256), bg(16,16);
  int gU=(NU+31)/32, gI=(NI+31)/32;
  int ggU=(NU+127)/128, ggI=(NI+127)/128;
  int nbU=(NU+255)/256, nbI=(NI+255)/256;

  k_init2<<<512,b256>>>(E_u_0,E_i_0,fuse_w,fuse_b,wv,W1u,W1i,b1,W2,b2,att_a,Wg);
  k_count<<<(NE+255)/256,b256>>>(esrc,edst);
  k_scanA<<<nbU+nbI,b256>>>(nbU);
  k_gemm2<<<ggU+ggI,bg>>>(E_u_0,W1u,b1,att_a, 0,bU1,bEu0,au,NU,
                          E_i_0,W1i,0,att_a+64, I1,0,bEi0,ai,NI,ggU);
  k_scanB<<<2,512>>>(nbU,nbI);
  k_scanC<<<nbU+nbI,b256>>>(nbU);
  k_fill<<<(NE+255)/256,b256>>>(esrc,edst,adj,dm,fuse_w,fuse_b,wv);

  // main propagation
  k_spmm2<<<gU+gI,b256>>>(rpu,pmu,colu,wm0u,1,0,bEi0,0,0,Eu1,bEu1,NU,
                          rpi,pmi,coli,wm0i,1,0,bEu0,0,0,Ei1,bEi1,NI,gU);
  k_spmm2<<<gU+gI,b256>>>(rpu,pmu,colu,wm1u,1,0,bEi1,E_u_0,Eu1,EuS,bEuS,NU,
                          rpi,pmi,coli,wm1i,1,0,bEu1,E_i_0,Ei1,EiS,bEiS,NI,gU);
  // GCN view
  k_spmm2<<<gU+gI,b256>>>(rpu,pmu,colu,wcu,1,0,bEiS,0,0,hu,0,NU,
                          rpi,pmi,coli,wci,1,0,bEuS,0,0,hi,0,NI,gU);
  k_gemm2<<<ggU,bg>>>(hu,Wg,0,0, 0,bHg,0,0,NU, 0,0,0,0,0,0,0,0,0,ggU);

  // edge passes
  k_edge1<<<(NI+7)/8,b256>>>(W2,b2);
  k_edge2<<<(NE+255)/256,b256>>>(fuse_w,fuse_b,adj,da);

  // augmented propagation (paired aug weights, stride-2)
  k_spmm2<<<gU+gI,b256>>>(rpu,pmu,colu,(const float*)wau,2,0,bEi0,0,0,Eu1,bEu1,NU,
                          rpi,pmi,coli,(const float*)wai,2,0,bEu0,0,0,Ei1,bEi1,NI,gU);
  k_spmm2<<<gU+gI,b256>>>(rpu,pmu,colu,(const float*)wau,2,1,bEi1,E_u_0,Eu1,Zu,0,NU,
                          rpi,pmi,coli,(const float*)wai,2,1,bEu1,E_i_0,Ei1,Zi,0,NI,gU);

  // losses (negsum + batch losses in one launch)
  int gxU=(NU+127)/128, gxI=(NI+127)/128;
  k_negsum2<<<dim3(gxU+gxI+1,BB/64),b256>>>(uids,iids,pos,neg,gxU,gxI);

  k_final<<<1,1024>>>(out);
}

// round 17
// speedup vs baseline: 1.4322x; 1.0044x over previous
#include <cuda_runtime.h>
#include <cuda_bf16.h>
#include <math.h>

#define NU 100000
#define NI 50000
#define NE 800000
#define BB 1024
typedef unsigned long long ull;

__device__ float g_Eu1[NU*64];
__device__ float g_EuS[NU*64];
__device__ float g_Hg [NU*64];
__device__ float g_hu [NU*64];
__device__ float g_Zu [NU*64];
__device__ float g_Ei1[NI*64];
__device__ float g_EiS[NI*64];
__device__ float g_I1 [NI*64];
__device__ float g_hi [NI*64];
__device__ float g_Zi [NI*64];
__device__ float g_au[NU];
__device__ float g_ai[NI];
__device__ __nv_bfloat16 g_bEu0[NU*64];
__device__ __nv_bfloat16 g_bEu1[NU*64];
__device__ __nv_bfloat16 g_bEuS[NU*64];
__device__ __nv_bfloat16 g_bU1 [NU*64];
__device__ __nv_bfloat16 g_bHg [NU*64];
__device__ __nv_bfloat16 g_bEi0[NI*64];
__device__ __nv_bfloat16 g_bEi1[NI*64];
__device__ __nv_bfloat16 g_bEiS[NI*64];
__device__ float4 g_views4[NE];
__device__ float g_pre[NE];
__device__ int   g_rowptr_u[NU+1];
__device__ int   g_rowptr_i[NI+1];
__device__ int   g_cur_u[NU];
__device__ int   g_cur_i[NI];
__device__ int   g_deg_u[NU];
__device__ int   g_deg_i[NI];
__device__ int   g_part_u[512];
__device__ int   g_part_i[512];
__device__ int   g_hist_u[256], g_hist_i[256];
__device__ int   g_curh_u[256], g_curh_i[256];
__device__ int   g_perm_u[NU], g_perm_i[NI];
__device__ int   g_col_u[NE];
__device__ int   g_col_i[NE];
__device__ int   g_eid_i[NE];
__device__ int   g_pos_u[NE];
__device__ int   g_pos_i[NE];
__device__ float g_fwi[NE], g_fbi[NE], g_wvi[NE];
__device__ float g_wcu[NE],  g_wci[NE];
__device__ float g_wm0u[NE], g_wm1u[NE];
__device__ float g_wm0i[NE], g_wm1i[NE];
__device__ float2 g_wa_u[NE];
__device__ float2 g_wa_i[NE];
__device__ double g_expsum[4];
__device__ double g_acc[4];     // 0: pr, 1: reg, 2: bpr, 3: pos
__device__ double g_negS[2*BB];

__device__ __forceinline__ float sigf(float x){ return 1.f/(1.f+__expf(-x)); }
__device__ __forceinline__ float tanha(float x){
  float y; asm("tanh.approx.f32 %0, %1;":"=f"(y):"f"(x)); return y;
}
__device__ __forceinline__ float ex2a(float x){
  float y; asm("ex2.approx.f32 %0, %1;":"=f"(y):"f"(x)); return y;
}
__device__ __forceinline__ unsigned tf32c(float f){
  unsigned u; asm("cvt.rna.tf32.f32 %0, %1;":"=r"(u):"f"(f)); return u;
}
__device__ __forceinline__ ull fma2(ull a, ull b, ull c){
  ull d;
  asm("fma.rn.f32x2 %0, %1, %2, %3;" : "=l"(d) : "l"(a), "l"(b), "l"(c));
  return d;
}
__device__ __forceinline__ ull bpair(unsigned raw){
  ull d;
  asm("mov.b64 %0,{%1,%2};":"=l"(d):"r"(raw<<16),"r"(raw&0xffff0000u));
  return d;
}
__device__ __forceinline__ float4 b2f4(uint2 raw){
  __nv_bfloat162 b0=*(__nv_bfloat162*)&raw.x, b1=*(__nv_bfloat162*)&raw.y;
  float2 f0=__bfloat1622float2(b0), f1=__bfloat1622float2(b1);
  return make_float4(f0.x,f0.y,f1.x,f1.y);
}
__device__ __forceinline__ uint2 f4b(float4 v){
  __nv_bfloat162 b0=__float22bfloat162_rn(make_float2(v.x,v.y));
  __nv_bfloat162 b1=__float22bfloat162_rn(make_float2(v.z,v.w));
  uint2 r; r.x=*(unsigned*)&b0; r.y=*(unsigned*)&b1; return r;
}
__device__ __forceinline__ float dot4(float4 a, float4 b){
  return a.x*b.x+a.y*b.y+a.z*b.z+a.w*b.w;
}

__global__ void k_init2(const float* __restrict__ Eu0, const float* __restrict__ Ei0,
                        const float* __restrict__ fw, const float* __restrict__ fb,
                        const float* __restrict__ wv,
                        const float* __restrict__ W1u, const float* __restrict__ W1i,
                        const float* __restrict__ b1, const float* __restrict__ W2,
                        const float* __restrict__ b2, const float* __restrict__ att_a,
                        const float* __restrict__ Wg){
  int i0=blockIdx.x*blockDim.x+threadIdx.x, st=gridDim.x*blockDim.x;
  for(int t=i0;t<NU;t+=st) g_deg_u[t]=0;
  for(int t=i0;t<NI;t+=st) g_deg_i[t]=0;
  for(int t=i0;t<2*BB;t+=st) g_negS[t]=0.0;
  if(i0<4){ g_expsum[i0]=0.0; g_acc[i0]=0.0; }
  if(i0<256){ g_hist_u[i0]=0; g_hist_i[i0]=0; }
  double s=0.0;
  for(int i=i0;i<NU*64;i+=st){ float v=Eu0[i]; s+=(double)v*(double)v; }
  for(int i=i0;i<NI*64;i+=st){ float v=Ei0[i]; s+=(double)v*(double)v; }
  for(int i=i0;i<NE;i+=st){
    float x=fw[i],y=fb[i],z=wv[i];
    s+=(double)x*x+(double)y*y+(double)z*z;
  }
  if(blockIdx.x==0){
    const float* ps[7]={W1u,W1i,b1,W2,b2,att_a,Wg};
    const int    ln[7]={4096,4096,64,64,1,128,4096};
    for(int a=0;a<7;a++){
      const float* p=ps[a];
      for(int i=threadIdx.x;i<ln[a];i+=blockDim.x){ float v=p[i]; s+=(double)v*(double)v; }
    }
  }
  #pragma unroll
  for(int o=16;o;o>>=1) s += __shfl_xor_sync(0xffffffffu,s,o);
  if((threadIdx.x&31)==0) atomicAdd(&g_acc[1],s);
}

__global__ void k_count(const int* __restrict__ src, const int* __restrict__ dst){
  int e=blockIdx.x*blockDim.x+threadIdx.x;
  if(e<NE){ atomicAdd(&g_deg_u[src[e]],1); atomicAdd(&g_deg_i[dst[e]],1); }
}

__global__ void k_scanA(int nbU){
  __shared__ int sh[256];
  __shared__ int hh[256];
  int bu=blockIdx.x<nbU;
  const int* deg = bu? g_deg_u : g_deg_i;
  int* part      = bu? g_part_u: g_part_i;
  int* gh        = bu? g_hist_u: g_hist_i;
  int blk = bu? blockIdx.x : blockIdx.x-nbU;
  int n = bu? NU:NI;
  int i=blk*256+threadIdx.x;
  int v=(i<n)?deg[i]:0;
  sh[threadIdx.x]=v;
  hh[threadIdx.x]=0;
  __syncthreads();
  if(i<n) atomicAdd(&hh[min(v,255)],1);
  for(int o=128;o;o>>=1){ if(threadIdx.x<o) sh[threadIdx.x]+=sh[threadIdx.x+o]; __syncthreads(); }
  if(threadIdx.x==0) part[blk]=sh[0];
  __syncthreads();
  if(hh[threadIdx.x]) atomicAdd(&gh[threadIdx.x],hh[threadIdx.x]);
}
__global__ void k_scanB(int nbU, int nbI){
  __shared__ int sh[512];
  int* part = blockIdx.x? g_part_i : g_part_u;
  int* hist = blockIdx.x? g_hist_i : g_hist_u;
  int* curh = blockIdx.x? g_curh_i : g_curh_u;
  int nb    = blockIdx.x? nbI : nbU;
  int t=threadIdx.x;
  int v=(t<nb)?part[t]:0;
  sh[t]=v; __syncthreads();
  for(int o=1;o<512;o<<=1){ int a=(t>=o)?sh[t-o]:0; __syncthreads(); sh[t]+=a; __syncthreads(); }
  if(t<nb) part[t]=sh[t]-v;
  __syncthreads();
  int hv=(t<256)?hist[t]:0;
  sh[t]=hv; __syncthreads();
  for(int o=1;o<256;o<<=1){
    int a=(t>=o && t<256)?sh[t-o]:0;
    __syncthreads();
    if(t<256) sh[t]+=a;
    __syncthreads();
  }
  if(t<256){ int ex=sh[t]-hv; hist[t]=ex; curh[t]=ex; }
}
__global__ void k_scanC(int nbU){
  __shared__ int sh[256];
  int bu=blockIdx.x<nbU;
  const int* deg = bu? g_deg_u : g_deg_i;
  const int* part= bu? g_part_u: g_part_i;
  int* rowptr    = bu? g_rowptr_u : g_rowptr_i;
  int* cur       = bu? g_cur_u : g_cur_i;
  int* curh      = bu? g_curh_u : g_curh_i;
  int* perm      = bu? g_perm_u : g_perm_i;
  int blk = bu? blockIdx.x : blockIdx.x-nbU;
  int n = bu? NU:NI;
  int i=blk*256+threadIdx.x;
  int v=(i<n)?deg[i]:0;
  sh[threadIdx.x]=v; __syncthreads();
  for(int o=1;o<256;o<<=1){ int a=(threadIdx.x>=o)?sh[threadIdx.x-o]:0; __syncthreads(); sh[threadIdx.x]+=a; __syncthreads(); }
  int excl=part[blk]+sh[threadIdx.x]-v;
  if(i<n){
    rowptr[i]=excl; cur[i]=excl;
    int pos=atomicAdd(&curh[min(v,255)],1);
    perm[pos]=i;
  }
  if(i==n-1) rowptr[n]=excl+v;
}

__global__ void k_fill(const int* __restrict__ src, const int* __restrict__ dst,
                       const float* __restrict__ adj, const float* __restrict__ dm,
                       const float* __restrict__ fw, const float* __restrict__ fb,
                       const float* __restrict__ wv){
  int e=blockIdx.x*blockDim.x+threadIdx.x;
  const float R=1.3333333333333333f;
  if(e<NE){
    int s=src[e], d=dst[e];
    float w=adj[e];
    float m0u=(dm[e]      >0.25f)? w*R:0.f;
    float m1u=(dm[2*NE+e] >0.25f)? w*R:0.f;
    float m0i=(dm[NE+e]   >0.25f)? w*R:0.f;
    float m1i=(dm[3*NE+e] >0.25f)? w*R:0.f;
    int p=atomicAdd(&g_cur_u[s],1);
    g_col_u[p]=d; g_wcu[p]=w; g_wm0u[p]=m0u; g_wm1u[p]=m1u;
    g_pos_u[e]=p;
    int q=atomicAdd(&g_cur_i[d],1);
    g_col_i[q]=s; g_eid_i[q]=e; g_wci[q]=w; g_wm0i[q]=m0i; g_wm1i[q]=m1i;
    g_fwi[q]=fw[e]; g_fbi[q]=fb[e]; g_wvi[q]=wv[e];
    g_pos_i[e]=q;
  }
}

// SpMM: perm rows high-degree-first; 8 warps x 4 rows/warp, 8 lanes/row
__device__ __forceinline__ void spmm_body(const int* rowptr, const int* perm, const int* col,
                       const float* w, int ws, int wo, const __nv_bfloat16* X,
                       const float* A, const float* Bv,
                       float* Y, __nv_bfloat16* Yb, int nrows, int blk){
  int tid=threadIdx.x;
  int warp=tid>>5, lane=tid&31;
  int quarter=lane>>3, sub=lane&7;
  int gr=blk*32 + warp*4 + quarter;
  int r = (gr<nrows)? perm[nrows-1-gr] : -1;
  int beg=0,end=0;
  if(r>=0){ beg=rowptr[r]; end=rowptr[r+1]; }
  int deg=end-beg;
  int md=deg;
  md=max(md,__shfl_xor_sync(0xffffffffu,md,8));
  md=max(md,__shfl_xor_sync(0xffffffffu,md,16));
  ull acc[2][4];
  #pragma unroll
  for(int s2=0;s2<2;s2++)
    #pragma unroll
    for(int q=0;q<4;q++) acc[s2][q]=0ull;
  for(int base=0;base<md;base+=8){
    int c=0; float v=0.f;
    if(base+sub<deg){ int j=beg+base+sub; c=col[j]; v=w[j*ws+wo]; }
    #pragma unroll
    for(int q=0;q<8;q++){
      float vq=__shfl_sync(0xffffffffu,v,q,8);
      int   cq=__shfl_sync(0xffffffffu,c,q,8);
      if(vq!=0.f){
        uint4 raw=*(const uint4*)(X+cq*64+sub*8);
        ull v2; asm("mov.b64 %0,{%1,%1};":"=l"(v2):"f"(vq));
        int s2=q&1;
        acc[s2][0]=fma2(bpair(raw.x),v2,acc[s2][0]);
        acc[s2][1]=fma2(bpair(raw.y),v2,acc[s2][1]);
        acc[s2][2]=fma2(bpair(raw.z),v2,acc[s2][2]);
        acc[s2][3]=fma2(bpair(raw.w),v2,acc[s2][3]);
      }
    }
  }
  if(r>=0){
    float f[8];
    #pragma unroll
    for(int q=0;q<4;q++){
      float l0,h0,l1,h1;
      asm("mov.b64 {%0,%1},%2;":"=f"(l0),"=f"(h0):"l"(acc[0][q]));
      asm("mov.b64 {%0,%1},%2;":"=f"(l1),"=f"(h1):"l"(acc[1][q]));
      f[2*q]=l0+l1; f[2*q+1]=h0+h1;
    }
    int o=r*64+sub*8;
    if(A){
      float4 a0=*(const float4*)&A[o], a1=*(const float4*)&A[o+4];
      f[0]+=a0.x; f[1]+=a0.y; f[2]+=a0.z; f[3]+=a0.w;
      f[4]+=a1.x; f[5]+=a1.y; f[6]+=a1.z; f[7]+=a1.w;
    }
    if(Bv){
      float4 b0=*(const float4*)&Bv[o], b1=*(const float4*)&Bv[o+4];
      f[0]+=b0.x; f[1]+=b0.y; f[2]+=b0.z; f[3]+=b0.w;
      f[4]+=b1.x; f[5]+=b1.y; f[6]+=b1.z; f[7]+=b1.w;
    }
    *(float4*)&Y[o]  =make_float4(f[0],f[1],f[2],f[3]);
    *(float4*)&Y[o+4]=make_float4(f[4],f[5],f[6],f[7]);
    if(Yb){
      uint2 p0=f4b(make_float4(f[0],f[1],f[2],f[3]));
      uint2 p1=f4b(make_float4(f[4],f[5],f[6],f[7]));
      uint4 pk; pk.x=p0.x; pk.y=p0.y; pk.z=p1.x; pk.w=p1.y;
      *(uint4*)(Yb+o)=pk;
    }
  }
}
__global__ void k_spmm2(const int* ra, const int* pa, const int* ca, const float* wa, int wsa, int woa,
                        const __nv_bfloat16* Xa,
                        const float* Aa, const float* Ba, float* Ya, __nv_bfloat16* Yba, int na,
                        const int* rb, const int* pb, const int* cb, const float* wb, int wsb, int wob,
                        const __nv_bfloat16* Xb,
                        const float* Ab, const float* Bb, float* Yb, __nv_bfloat16* Ybb, int nb, int gA){
  if((int)blockIdx.x<gA) spmm_body(ra,pa,ca,wa,wsa,woa,Xa,Aa,Ba,Ya,Yba,na,blockIdx.x);
  else                   spmm_body(rb,pb,cb,wb,wsb,wob,Xb,Ab,Bb,Yb,Ybb,nb,blockIdx.x-gA);
}

// node GEMM: 128 rows/block, 8 rows x 4 cols per thread, transposed X tile.
__device__ __forceinline__ void gemm_body(const float* X, const float* W,
                            const float* bias, const float* att,
                            float* Y, __nv_bfloat16* Yb, __nv_bfloat16* Xb,
                            float* attOut, int n, int blk){
  __shared__ float Ws[4096];
  __shared__ float XsT[64][132];
  __shared__ float atts[64];
  int tx=threadIdx.x, ty=threadIdx.y;
  int tid=ty*16+tx;
  for(int t=tid;t<1024;t+=256) ((float4*)Ws)[t]=((const float4*)W)[t];
  if(att && tid<64) atts[tid]=att[tid];
  int rbase=blk*128;
  #pragma unroll
  for(int it=0;it<8;it++){
    int t=tid+256*it;
    int row=t>>4, c16=t&15;
    int r=rbase+row;
    float4 x = (r<n)? ((const float4*)&X[r*64])[c16] : make_float4(0.f,0.f,0.f,0.f);
    int c4=c16*4;
    XsT[c4+0][row]=x.x; XsT[c4+1][row]=x.y; XsT[c4+2][row]=x.z; XsT[c4+3][row]=x.w;
    if(Xb && r<n) *(uint2*)(Xb+r*64+c4)=f4b(x);
  }
  __syncthreads();
  float4 bv = bias ? ((const float4*)bias)[tx] : make_float4(0.f,0.f,0.f,0.f);
  float4 acc[8];
  #pragma unroll
  for(int q=0;q<8;q++) acc[q]=bv;
  #pragma unroll
  for(int k=0;k<64;k++){
    float4 wv=((const float4*)&Ws[k*64])[tx];
    float4 xa=*(const float4*)&XsT[k][ty*8];
    float4 xb2=*(const float4*)&XsT[k][ty*8+4];
    acc[0].x+=xa.x*wv.x; acc[0].y+=xa.x*wv.y; acc[0].z+=xa.x*wv.z; acc[0].w+=xa.x*wv.w;
    acc[1].x+=xa.y*wv.x; acc[1].y+=xa.y*wv.y; acc[1].z+=xa.y*wv.z; acc[1].w+=xa.y*wv.w;
    acc[2].x+=xa.z*wv.x; acc[2].y+=xa.z*wv.y; acc[2].z+=xa.z*wv.z; acc[2].w+=xa.z*wv.w;
    acc[3].x+=xa.w*wv.x; acc[3].y+=xa.w*wv.y; acc[3].z+=xa.w*wv.z; acc[3].w+=xa.w*wv.w;
    acc[4].x+=xb2.x*wv.x; acc[4].y+=xb2.x*wv.y; acc[4].z+=xb2.x*wv.z; acc[4].w+=xb2.x*wv.w;
    acc[5].x+=xb2.y*wv.x; acc[5].y+=xb2.y*wv.y; acc[5].z+=xb2.y*wv.z; acc[5].w+=xb2.y*wv.w;
    acc[6].x+=xb2.z*wv.x; acc[6].y+=xb2.z*wv.y; acc[6].z+=xb2.z*wv.z; acc[6].w+=xb2.z*wv.w;
    acc[7].x+=xb2.w*wv.x; acc[7].y+=xb2.w*wv.y; acc[7].z+=xb2.w*wv.z; acc[7].w+=xb2.w*wv.w;
  }
  #pragma unroll
  for(int q=0;q<8;q++){
    int row=rbase+ty*8+q;
    if(row<n){
      if(Y) ((float4*)&Y[row*64])[tx]=acc[q];
      if(Yb) *(uint2*)(Yb+row*64+tx*4)=f4b(acc[q]);
    }
  }
  if(att){
    #pragma unroll
    for(int q=0;q<8;q++){
      int row=rbase+ty*8+q;
      float p=0.f;
      #pragma unroll
      for(int i=0;i<4;i++) p+=XsT[tx*4+i][ty*8+q]*atts[tx*4+i];
      #pragma unroll
      for(int o=8;o;o>>=1) p+=__shfl_xor_sync(0xffffffffu,p,o,16);
      if(tx==0 && row<n) attOut[row]=p;
    }
  }
}
__global__ void k_gemm2(const float* Xa, const float* Wa, const float* ba, const float* aa,
                        float* Ya, __nv_bfloat16* Yba, __nv_bfloat16* Xba, float* aoa, int na,
                        const float* Xb, const float* Wb, const float* bb, const float* ab,
                        float* Yb, __nv_bfloat16* Ybb, __nv_bfloat16* Xbb, float* aob, int nb, int gA){
  if((int)blockIdx.x<gA) gemm_body(Xa,Wa,ba,aa,Ya,Yba,Xba,aoa,na,blockIdx.x);
  else                   gemm_body(Xb,Wb,bb,ab,Yb,Ybb,Xbb,aob,nb,blockIdx.x-gA);
}

// edge views: perm-sorted item rows (high-degree first), warp per row,
// 4 edges x 8 lanes x uint4 bf16 gathers
__global__ void k_edge1(const float* __restrict__ W2, const float* __restrict__ b2){
  __shared__ float W2s[64];
  __shared__ double sacc[4];
  int tid=threadIdx.x, lane=tid&31, warp=tid>>5;
  int grp=lane>>3, sub=lane&7;
  if(tid<64) W2s[tid]=W2[tid];
  if(tid<4)  sacc[tid]=0.0;
  __syncthreads();
  int slot=blockIdx.x*8+warp;
  int r = (slot<NI)? g_perm_i[NI-1-slot] : -1;
  float e0=0.f,e1=0.f,e2=0.f,e3=0.f;
  if(r>=0){
    float b2v=b2[0];
    float4 w2a=((const float4*)W2s)[sub*2],  w2b=((const float4*)W2s)[sub*2+1];
    float4 i1a=*(const float4*)&g_I1 [r*64+sub*8], i1b=*(const float4*)&g_I1 [r*64+sub*8+4];
    float4 hia=*(const float4*)&g_hi [r*64+sub*8], hib=*(const float4*)&g_hi [r*64+sub*8+4];
    float4 sia=*(const float4*)&g_EiS[r*64+sub*8], sib=*(const float4*)&g_EiS[r*64+sub*8+4];
    float aiv=g_ai[r];
    int beg=g_rowptr_i[r], end=g_rowptr_i[r+1];
    for(int j0=beg;j0<end;j0+=4){
      int j=j0+grp;
      bool act=(j<end);
      int u=g_col_i[act? j : end-1];
      uint4 ru=*(const uint4*)(g_bU1 +u*64+sub*8);
      uint4 rh=*(const uint4*)(g_bHg +u*64+sub*8);
      uint4 rs=*(const uint4*)(g_bEuS+u*64+sub*8);
      float4 u1a=b2f4(make_uint2(ru.x,ru.y)), u1b=b2f4(make_uint2(ru.z,ru.w));
      float4 hga=b2f4(make_uint2(rh.x,rh.y)), hgb=b2f4(make_uint2(rh.z,rh.w));
      float4 sua=b2f4(make_uint2(rs.x,rs.y)), sub4=b2f4(make_uint2(rs.z,rs.w));
      float m  = fmaxf(u1a.x+i1a.x,0.f)*w2a.x + fmaxf(u1a.y+i1a.y,0.f)*w2a.y
               + fmaxf(u1a.z+i1a.z,0.f)*w2a.z + fmaxf(u1a.w+i1a.w,0.f)*w2a.w
               + fmaxf(u1b.x+i1b.x,0.f)*w2b.x + fmaxf(u1b.y+i1b.y,0.f)*w2b.y
               + fmaxf(u1b.z+i1b.z,0.f)*w2b.z + fmaxf(u1b.w+i1b.w,0.f)*w2b.w;
      float gc = dot4(hga,hia)+dot4(hgb,hib);
      float pr = dot4(sua,sia)+dot4(sub4,sib);
      #pragma unroll
      for(int o=4;o;o>>=1){
        m +=__shfl_xor_sync(0xffffffffu,m,o,8);
        gc+=__shfl_xor_sync(0xffffffffu,gc,o,8);
        pr+=__shfl_xor_sync(0xffffffffu,pr,o,8);
      }
      if(act && sub==0){
        int e=g_eid_i[j];
        float v0=sigf(m+b2v);
        float v1=sigf(g_wvi[j]);
        float v2=sigf(gc);
        float a=g_au[u]+aiv;
        float v3=sigf(a>0.f? a : 0.2f*a);
        g_views4[e]=make_float4(v0,v1,v2,v3);
        g_pre[e]=sigf(pr);
        float w=g_fwi[j], b=g_fbi[j];
        e0+=__expf(tanha(w*v0+b));
        e1+=__expf(tanha(w*v1+b));
        e2+=__expf(tanha(w*v2+b));
        e3+=__expf(tanha(w*v3+b));
      }
    }
  }
  e0+=__shfl_xor_sync(0xffffffffu,e0,8);  e0+=__shfl_xor_sync(0xffffffffu,e0,16);
  e1+=__shfl_xor_sync(0xffffffffu,e1,8);  e1+=__shfl_xor_sync(0xffffffffu,e1,16);
  e2+=__shfl_xor_sync(0xffffffffu,e2,8);  e2+=__shfl_xor_sync(0xffffffffu,e2,16);
  e3+=__shfl_xor_sync(0xffffffffu,e3,8);  e3+=__shfl_xor_sync(0xffffffffu,e3,16);
  if(lane==0 && r>=0){
    atomicAdd(&sacc[0],(double)e0);
    atomicAdd(&sacc[1],(double)e1);
    atomicAdd(&sacc[2],(double)e2);
    atomicAdd(&sacc[3],(double)e3);
  }
  __syncthreads();
  if(tid<4) atomicAdd(&g_expsum[tid],sacc[tid]);
}

__global__ void k_edge2(const float* __restrict__ fw, const float* __restrict__ fb,
                        const float* __restrict__ adj, const float* __restrict__ da){
  int e=blockIdx.x*blockDim.x+threadIdx.x;
  const float R=1.3333333333333333f;
  float lp=0.f;
  if(e<NE){
    float S0=(float)g_expsum[0], S1=(float)g_expsum[1];
    float S2=(float)g_expsum[2], S3=(float)g_expsum[3];
    float w=fw[e], b=fb[e];
    float4 v=g_views4[e];
    float Ag = __expf(tanha(w*v.x+b))/S0*v.x
             + __expf(tanha(w*v.y+b))/S1*v.y
             + __expf(tanha(w*v.z+b))/S2*v.z
             + __expf(tanha(w*v.w+b))/S3*v.w;
    float sumv=v.x+v.y+v.z+v.w;
    float baew=g_pre[e]*((sumv-3.f*Ag)*0.2f);
    float augw=baew*adj[e];
    int pu=g_pos_u[e], pi=g_pos_i[e];
    float a0u=(da[e]      >0.25f)? augw*R:0.f;
    float a1u=(da[2*NE+e] >0.25f)? augw*R:0.f;
    float a0i=(da[NE+e]   >0.25f)? augw*R:0.f;
    float a1i=(da[3*NE+e] >0.25f)? augw*R:0.f;
    g_wa_u[pu]=make_float2(a0u,a1u);
    g_wa_i[pi]=make_float2(a0i,a1i);
    lp=-__logf(baew);
  }
  #pragma unroll
  for(int o=16;o;o>>=1) lp += __shfl_xor_sync(0xffffffffu,lp,o);
  if((threadIdx.x&31)==0) atomicAdd(&g_acc[0],(double)lp);
}

__device__ __forceinline__ void small_body(const int* uids, const int* iids,
                                           const int* pos, const int* neg){
  int warpG=blockIdx.y*8 + (threadIdx.x>>5);
  int l=threadIdx.x&31;
  for(int k=0;k<8;k++){
    int w=warpG+128*k;
    if(w>=BB) break;
    int u=uids[w], it=iids[w], p=pos[w], ng=neg[w];
    float dzu=0,dzi=0,dup=0,dun=0;
    #pragma unroll
    for(int d=l; d<64; d+=32){
      float eu=g_EuS[u*64+d];
      dzu += g_Zu[u*64+d]*eu;
      dzi += g_Zi[it*64+d]*g_EiS[it*64+d];
      dup += eu*g_EiS[p*64+d];
      dun += eu*g_EiS[ng*64+d];
    }
    #pragma unroll
    for(int o=16;o;o>>=1){
      dzu+=__shfl_xor_sync(0xffffffffu,dzu,o);
      dzi+=__shfl_xor_sync(0xffffffffu,dzi,o);
      dup+=__shfl_xor_sync(0xffffffffu,dup,o);
      dun+=__shfl_xor_sync(0xffffffffu,dun,o);
    }
    if(l==0){
      float cu=fminf(fmaxf(dzu*5.f,-5.f),5.f);
      float ci=fminf(fmaxf(dzi*5.f,-5.f),5.f);
      float diff=dup-dun;
      float bpr=fmaxf(-diff,0.f)+log1pf(expf(-fabsf(diff)));
      atomicAdd(&g_acc[3],(double)(cu+ci));
      atomicAdd(&g_acc[2],(double)bpr);
    }
  }
}

__device__ __forceinline__ void negsum_body(const int* ids, const float* Z,
                                            const __nv_bfloat16* Xb, int N, int isItem, int bx){
  __shared__ unsigned Gs[64][68];
  __shared__ unsigned Xs[128][68];
  __shared__ float Ps[64][8];
  int b0=blockIdx.y*64, j0=bx*128;
  int tid=threadIdx.x;
  const float scale=7.213475204444817f; // log2(e)/0.2
  for(int idx=tid; idx<64*16; idx+=256){
    int r=idx>>4, c4=(idx&15)*4;
    float4 g=*(const float4*)&Z[ids[b0+r]*64+c4];
    Gs[r][c4+0]=tf32c(g.x*scale); Gs[r][c4+1]=tf32c(g.y*scale);
    Gs[r][c4+2]=tf32c(g.z*scale); Gs[r][c4+3]=tf32c(g.w*scale);
  }
  for(int idx=tid; idx<128*16; idx+=256){
    int r=idx>>4, c4=(idx&15)*4;
    int j=j0+r;
    uint2 raw = (j<N)? *(const uint2*)(Xb+j*64+c4) : make_uint2(0u,0u);
    Xs[r][c4+0]=raw.x<<16; Xs[r][c4+1]=raw.x&0xffff0000u;
    Xs[r][c4+2]=raw.y<<16; Xs[r][c4+3]=raw.y&0xffff0000u;
  }
  __syncthreads();
  int w=tid>>5, lane=tid&31;
  int g=lane>>2, t=lane&3;
  int brow=(w&3)*16, jbase=(w>>2)*64;
  float c[8][4];
  #pragma unroll
  for(int nt=0;nt<8;nt++)
    #pragma unroll
    for(int q=0;q<4;q++) c[nt][q]=0.f;
  #pragma unroll
  for(int k0=0;k0<64;k0+=8){
    unsigned a0=Gs[brow+g][k0+t],   a1=Gs[brow+g+8][k0+t];
    unsigned a2=Gs[brow+g][k0+t+4], a3=Gs[brow+g+8][k0+t+4];
    #pragma unroll
    for(int nt=0;nt<8;nt++){
      unsigned bb0=Xs[jbase+nt*8+g][k0+t], bb1=Xs[jbase+nt*8+g][k0+t+4];
      asm volatile("mma.sync.aligned.m16n8k8.row.col.f32.tf32.tf32.f32 "
        "{%0,%1,%2,%3}, {%4,%5,%6,%7}, {%8,%9}, {%0,%1,%2,%3};"
        : "+f"(c[nt][0]),"+f"(c[nt][1]),"+f"(c[nt][2]),"+f"(c[nt][3])
        : "r"(a0),"r"(a1),"r"(a2),"r"(a3),"r"(bb0),"r"(bb1));
    }
  }
  float s0=0.f, s1=0.f;
  #pragma unroll
  for(int nt=0;nt<8;nt++){
    int col=j0+jbase+nt*8+2*t;
    if(col<N)   { s0+=ex2a(c[nt][0]); s1+=ex2a(c[nt][2]); }
    if(col+1<N) { s0+=ex2a(c[nt][1]); s1+=ex2a(c[nt][3]); }
  }
  int slot=(w>>2)*4+t;
  Ps[brow+g][slot]=s0;
  Ps[brow+g+8][slot]=s1;
  __syncthreads();
  if(tid<64){
    float s=0.f;
    #pragma unroll
    for(int q=0;q<8;q++) s+=Ps[tid][q];
    atomicAdd(&g_negS[isItem*BB + b0 + tid],(double)s);
  }
}
__global__ void k_negsum2(const int* uids, const int* iids,
                          const int* pos, const int* neg, int gxU, int gxI){
  if((int)blockIdx.x<gxU) negsum_body(uids,g_Zu,g_bEuS,NU,0,blockIdx.x);
  else if((int)blockIdx.x<gxU+gxI) negsum_body(iids,g_Zi,g_bEiS,NI,1,blockIdx.x-gxU);
  else small_body(uids,iids,pos,neg);
}

__global__ void k_final(float* __restrict__ out){
  __shared__ double sh[1024];
  int t=threadIdx.x;
  sh[t]=log(g_negS[t]+1e-8)+log(g_negS[BB+t]+1e-8);
  __syncthreads();
  for(int o=512;o;o>>=1){ if(t<o) sh[t]+=sh[t+o]; __syncthreads(); }
  if(t==0){
    double neg=sh[0]/(double)BB;
    double pos=g_acc[3]/(double)BB;
    double cl=-pos+neg;
    double bpr=g_acc[2]/(double)BB;
    double pr=0.01*(g_acc[0]/(double)NE);
    double reg=1e-5*g_acc[1];
    out[0]=(float)(bpr+0.2*cl+pr+reg);
    out[1]=(float)bpr;
    out[2]=(float)(0.2*cl);
    out[3]=(float)pr;
  }
}

#define GA(p,s) do{ void* t_=0; cudaGetSymbolAddress(&t_,s); p=(decltype(p))t_; }while(0)

extern "C" void kernel_launch(void* const* d_in, const int* in_sizes, int n_in,
                              void* d_out, int out_size){
  const float* E_u_0 =(const float*)d_in[0];
  const float* E_i_0 =(const float*)d_in[1];
  const float* fuse_w=(const float*)d_in[2];
  const float* fuse_b=(const float*)d_in[3];
  const float* W1u   =(const float*)d_in[4];
  const float* W1i   =(const float*)d_in[5];
  const float* b1    =(const float*)d_in[6];
  const float* W2    =(const float*)d_in[7];
  const float* b2    =(const float*)d_in[8];
  const float* att_a =(const float*)d_in[9];
  const float* wv    =(const float*)d_in[10];
  const float* Wg    =(const float*)d_in[11];
  const float* adj   =(const float*)d_in[12];
  const float* dm    =(const float*)d_in[13];
  const float* da    =(const float*)d_in[14];
  const int* esrc=(const int*)d_in[15];
  const int* edst=(const int*)d_in[16];
  const int* uids=(const int*)d_in[17];
  const int* iids=(const int*)d_in[18];
  const int* pos =(const int*)d_in[19];
  const int* neg =(const int*)d_in[20];
  float* out=(float*)d_out;

  float *Eu1,*EuS,*Hg,*hu,*Zu,*Ei1,*EiS,*I1,*hi,*Zi,*au,*ai;
  float *wcu,*wci,*wm0u,*wm1u,*wm0i,*wm1i;
  float2 *wau,*wai;
  __nv_bfloat16 *bEu0,*bEu1,*bEuS,*bU1,*bHg,*bEi0,*bEi1,*bEiS;
  int *rpu,*rpi,*colu,*coli,*pmu,*pmi;
  GA(Eu1,g_Eu1); GA(EuS,g_EuS); GA(Hg,g_Hg);
  GA(hu,g_hu); GA(Zu,g_Zu); GA(Ei1,g_Ei1); GA(EiS,g_EiS);
  GA(I1,g_I1); GA(hi,g_hi); GA(Zi,g_Zi); GA(au,g_au); GA(ai,g_ai);
  GA(bEu0,g_bEu0); GA(bEu1,g_bEu1); GA(bEuS,g_bEuS); GA(bU1,g_bU1); GA(bHg,g_bHg);
  GA(bEi0,g_bEi0); GA(bEi1,g_bEi1); GA(bEiS,g_bEiS);
  GA(wcu,g_wcu); GA(wci,g_wci); GA(wm0u,g_wm0u); GA(wm1u,g_wm1u);
  GA(wm0i,g_wm0i); GA(wm1i,g_wm1i); GA(wau,g_wa_u); GA(wai,g_wa_i);
  GA(rpu,g_rowptr_u); GA(rpi,g_rowptr_i);
  GA(colu,g_col_u); GA(coli,g_col_i);
  GA(pmu,g_perm_u); GA(pmi,g_perm_i);

  dim3 b256(256), bg(16,16);
  int gU=(NU+31)/32, gI=(NI+31)/32;
  int ggU=(NU+127)/128, ggI=(NI+127)/128;
  int nbU=(NU+255)/256, nbI=(NI+255)/256;

  k_init2<<<512,b256>>>(E_u_0,E_i_0,fuse_w,fuse_b,wv,W1u,W1i,b1,W2,b2,att_a,Wg);
  k_count<<<(NE+255)/256,b256>>>(esrc,edst);
  k_scanA<<<nbU+nbI,b256>>>(nbU);
  k_gemm2<<<ggU+ggI,bg>>>(E_u_0,W1u,b1,att_a, 0,bU1,bEu0,au,NU,
                          E_i_0,W1i,0,att_a+64, I1,0,bEi0,ai,NI,ggU);
  k_scanB<<<2,512>>>(nbU,nbI);
  k_scanC<<<nbU+nbI,b256>>>(nbU);
  k_fill<<<(NE+255)/256,b256>>>(esrc,edst,adj,dm,fuse_w,fuse_b,wv);

  // main propagation
  k_spmm2<<<gU+gI,b256>>>(rpu,pmu,colu,wm0u,1,0,bEi0,0,0,Eu1,bEu1,NU,
                          rpi,pmi,coli,wm0i,1,0,bEu0,0,0,Ei1,bEi1,NI,gU);
  k_spmm2<<<gU+gI,b256>>>(rpu,pmu,colu,wm1u,1,0,bEi1,E_u_0,Eu1,EuS,bEuS,NU,
                          rpi,pmi,coli,wm1i,1,0,bEu1,E_i_0,Ei1,EiS,bEiS,NI,gU);
  // GCN view
  k_spmm2<<<gU+gI,b256>>>(rpu,pmu,colu,wcu,1,0,bEiS,0,0,hu,0,NU,
                          rpi,pmi,coli,wci,1,0,bEuS,0,0,hi,0,NI,gU);
  k_gemm2<<<ggU,bg>>>(hu,Wg,0,0, 0,bHg,0,0,NU, 0,0,0,0,0,0,0,0,0,ggU);

  // edge passes
  k_edge1<<<(NI+7)/8,b256>>>(W2,b2);
  k_edge2<<<(NE+255)/256,b256>>>(fuse_w,fuse_b,adj,da);

  // augmented propagation (paired aug weights, stride-2)
  k_spmm2<<<gU+gI,b256>>>(rpu,pmu,colu,(const float*)wau,2,0,bEi0,0,0,Eu1,bEu1,NU,
                          rpi,pmi,coli,(const float*)wai,2,0,bEu0,0,0,Ei1,bEi1,NI,gU);
  k_spmm2<<<gU+gI,b256>>>(rpu,pmu,colu,(const float*)wau,2,1,bEi1,E_u_0,Eu1,Zu,0,NU,
                          rpi,pmi,coli,(const float*)wai,2,1,bEu1,E_i_0,Ei1,Zi,0,NI,gU);

  // losses (negsum + batch losses in one launch)
  int gxU=(NU+127)/128, gxI=(NI+127)/128;
  k_negsum2<<<dim3(gxU+gxI+1,BB/64),b256>>>(uids,iids,pos,neg,gxU,gxI);

  k_final<<<1,1024>>>(out);
}